// round 10
// baseline (speedup 1.0000x reference)
#include <cuda_runtime.h>
#include <cuda_fp16.h>
#include <mma.h>
#include <math.h>

using namespace nvcuda;

#define NN    512
#define FF    128
#define HH    256
#define MM    256
#define DEGN  8
#define HISTN 10
#define OO    64
#define PPV   2
#define MAXS  (10*NN)     /* 5120 */
#define NLVL  6
#define PCAP  640         /* max parents with children: ceil((MAXS-1)/8) */
#define BM    64
#define BN    64
#define BK    16

/* -------- persistent scratch (device globals; no allocation allowed) ------ */
__device__ float g_hist [NN*HISTN*HH];                    // node state rings (fp32)
__device__ __align__(16) __half g_XF  [NN*512];           // [KQ|W2] for steps s<S
__device__ __align__(16) __half g_CH  [PCAP*512];         // [KQ|W2] for children of parent p
__device__ __align__(16) __half g_ns_h[PCAP*HH];          // NS rows (parents only)
__device__ __align__(16) __half g_BB  [512*512];          // rows 0..255 = D, 256..511 = E=[A|Wm2]
__device__ __align__(16) __half g_wm1h[HH*HH];            // Wm rows 0..255 fp16
__device__ __align__(16) __half g_wr_h[HH*HH];            // Wr_sum fp16
__device__ __align__(16) __half g_fm_h[NN*MM];            // first_message fp16
__device__ float g_bias [512];                            // [bqk | bm]
__device__ int   g_bucket[MAXS];
__device__ int   g_boff  [NN+1];
__device__ int   g_count [NN];

/* ---- level bounds: level l covers steps [lo, hi) -------------------------- */
__device__ __forceinline__ void level_bounds(int S, int level, int* plo, int* phi)
{
    int lo = 0, hi = (S < MAXS) ? S : MAXS;
    for (int l = 0; l < level; ++l) {
        lo = hi;
        int h2 = S + 8*hi;
        hi = (h2 > MAXS) ? MAXS : h2;
    }
    *plo = lo; *phi = hi;
}

/* ------ K1: encode + fp16 packs (fm, Wm1, Wr_sum) ------------------------- */
__global__ void k_encode(const float* __restrict__ xa, const float* __restrict__ We,
                         const float* __restrict__ be, const float* __restrict__ fm,
                         const float* __restrict__ Wm, const float* __restrict__ Wr)
{
    __shared__ float sx[FF];
    int n = blockIdx.x, t = threadIdx.x;
    if (t < FF) sx[t] = xa[n*FF + t];
    __syncthreads();
    float acc = be[t];
    #pragma unroll 4
    for (int f = 0; f < FF; ++f) acc += sx[f] * We[f*HH + t];
    g_hist[((size_t)n*HISTN + 0)*HH + t] = acc;
    if (t == 0) g_count[n] = 1;
    g_fm_h[(size_t)n*MM + t] = __float2half(fm[(size_t)n*MM + t]);
    if (n < HH) {
        g_wm1h[(size_t)n*MM + t] = __float2half(Wm[(size_t)n*MM + t]);
        float s = Wr[n*HH + t] + Wr[(HH + n)*HH + t]
                + Wr[(2*HH + n)*HH + t] + Wr[(3*HH + n)*HH + t];
        g_wr_h[n*HH + t] = __float2half(s);
    }
}

/* ------ K2: A = Wq@Wk^T -> BB rows 256.., cols 0..255; pack Wm2 + bias ---- */
__global__ void __launch_bounds__(256) k_gemmA(const float* __restrict__ Wq,
                                               const float* __restrict__ Wk,
                                               const float* __restrict__ Wm,
                                               const float* __restrict__ bq,
                                               const float* __restrict__ bm)
{
    const int bx = blockIdx.x, by = blockIdx.y;
    const int t = threadIdx.x;
    if (bx >= 4) {
        /* pack Wm2 tile into BB rows 256.., cols 256.. */
        int k0 = (bx-4)*64, j0 = by*64;
        for (int i = t; i < 64*64; i += 256) {
            int k = k0 + (i >> 6), j = j0 + (i & 63);
            g_BB[(size_t)(256 + k)*512 + 256 + j] =
                __float2half(Wm[(size_t)(256 + k)*MM + j]);
        }
        if (bx == 4 && by == 0) {      /* bias = [Wk@bq | bm] */
            int w = t >> 5, l = t & 31;
            for (int r0 = 0; r0 < HH; r0 += 8) {
                int r = r0 + w;
                float p = 0.f;
                #pragma unroll
                for (int k = 0; k < 8; ++k) { int h = l + k*32; p += Wk[(size_t)r*HH + h]*bq[h]; }
                #pragma unroll
                for (int o = 16; o > 0; o >>= 1) p += __shfl_down_sync(0xffffffffu, p, o);
                if (l == 0) g_bias[r] = p;
            }
            if (t < HH) g_bias[256 + t] = bm[t];
        }
        return;
    }
    /* A[i][j] = sum_h Wq[i][h]*Wk[j][h], 64x64 tile, thread = 4x4 outputs */
    __shared__ float sA[16][65], sB[16][65];
    const int i0 = bx*64, j0 = by*64;
    const int tx = t & 15, ty = t >> 4;
    float acc[4][4];
    #pragma unroll
    for (int a = 0; a < 4; ++a)
        #pragma unroll
        for (int b = 0; b < 4; ++b) acc[a][b] = 0.f;
    for (int kt = 0; kt < HH; kt += 16) {
        int lr = t >> 2, lh = (t & 3)*4;
        float4 va = *(const float4*)(Wq + (size_t)(i0+lr)*HH + kt + lh);
        sA[lh+0][lr]=va.x; sA[lh+1][lr]=va.y; sA[lh+2][lr]=va.z; sA[lh+3][lr]=va.w;
        float4 vb = *(const float4*)(Wk + (size_t)(j0+lr)*HH + kt + lh);
        sB[lh+0][lr]=vb.x; sB[lh+1][lr]=vb.y; sB[lh+2][lr]=vb.z; sB[lh+3][lr]=vb.w;
        __syncthreads();
        #pragma unroll
        for (int h = 0; h < 16; ++h) {
            float ra[4], rb[4];
            #pragma unroll
            for (int a = 0; a < 4; ++a) ra[a] = sA[h][ty*4 + a];
            #pragma unroll
            for (int b = 0; b < 4; ++b) rb[b] = sB[h][tx*4 + b];
            #pragma unroll
            for (int a = 0; a < 4; ++a)
                #pragma unroll
                for (int b = 0; b < 4; ++b) acc[a][b] += ra[a]*rb[b];
        }
        __syncthreads();
    }
    #pragma unroll
    for (int a = 0; a < 4; ++a)
        #pragma unroll
        for (int b = 0; b < 4; ++b)
            g_BB[(size_t)(256 + i0 + ty*4 + a)*512 + (j0 + tx*4 + b)] =
                __float2half(acc[a][b]);
}

/* ------ K3: D = Wm1 @ E (fp16 wmma) -> BB rows 0..255 --------------------- */
__global__ void __launch_bounds__(256) k_gemmD()
{
    __shared__ __half sA[BM][BK];
    __shared__ __half sB[BK][BN];
    __shared__ float  sO[BM][BN];
    const int m0 = blockIdx.x * BM;     /* grid (4, 8) */
    const int n0 = blockIdx.y * BN;
    const int tid = threadIdx.x;
    const int wid = tid >> 5, wr = wid & 3, wc = wid >> 2;
    wmma::fragment<wmma::accumulator,16,16,16,float> acc[2];
    wmma::fill_fragment(acc[0], 0.f);
    wmma::fill_fragment(acc[1], 0.f);
    const int ar = tid >> 2, ac = (tid & 3)*4;
    const int brw = tid >> 4, bc = (tid & 15)*4;
    for (int kt = 0; kt < HH; kt += BK) {
        *(uint2*)&sA[ar][ac] = *(const uint2*)(g_wm1h + (size_t)(m0+ar)*HH + kt + ac);
        *(uint2*)&sB[brw][bc] = *(const uint2*)(g_BB + (size_t)(256 + kt + brw)*512 + n0 + bc);
        __syncthreads();
        wmma::fragment<wmma::matrix_a,16,16,16,__half,wmma::row_major> fa;
        wmma::load_matrix_sync(fa, &sA[wr*16][0], BK);
        #pragma unroll
        for (int j = 0; j < 2; ++j) {
            wmma::fragment<wmma::matrix_b,16,16,16,__half,wmma::row_major> fb;
            wmma::load_matrix_sync(fb, &sB[0][wc*32 + j*16], BN);
            wmma::mma_sync(acc[j], fa, fb, acc[j]);
        }
        __syncthreads();
    }
    wmma::store_matrix_sync(&sO[wr*16][wc*32],      acc[0], BN, wmma::mem_row_major);
    wmma::store_matrix_sync(&sO[wr*16][wc*32 + 16], acc[1], BN, wmma::mem_row_major);
    __syncthreads();
    for (int idx = tid; idx < BM*BN; idx += 256) {
        int r = idx >> 6, nl = idx & 63;
        g_BB[(size_t)(m0 + r)*512 + n0 + nl] = __float2half(sO[r][nl]);
    }
}

/* ------- K4: node sequence + per-node sorted step buckets ----------------- */
__global__ void k_graph(const int* __restrict__ neighbors, const int* __restrict__ ns_ptr)
{
    __shared__ int sn[MAXS];   // 20 KB
    __shared__ int T[NN], P[NN], cur[NN];
    int t = threadIdx.x;       // 512 threads
    int S = *ns_ptr;
    for (int e = t; e < S && e < MAXS; e += 512) sn[e] = e;
    __syncthreads();
    int known = (S < MAXS) ? S : MAXS;
    while (known < MAXS) {
        long long nx = (long long)S + 8LL*(long long)known;
        int next = (nx > MAXS) ? MAXS : (int)nx;
        for (int e = known + t; e < next; e += 512) {
            int src = (e - S) >> 3;
            sn[e] = neighbors[sn[src]*DEGN + ((e - S) & 7)];
        }
        __syncthreads();
        known = next;
    }
    T[t] = 0; cur[t] = 0;
    __syncthreads();
    for (int e = t; e < MAXS; e += 512) atomicAdd(&T[sn[e]], 1);
    __syncthreads();
    P[t] = T[t];
    __syncthreads();
    for (int o = 1; o < NN; o <<= 1) {
        int v = (t >= o) ? P[t-o] : 0;
        __syncthreads();
        P[t] += v;
        __syncthreads();
    }
    g_boff[t] = P[t] - T[t];
    if (t == NN-1) g_boff[NN] = P[t];
    __syncthreads();
    for (int e = t; e < MAXS; e += 512) {
        int nd = sn[e];
        int pos = atomicAdd(&cur[nd], 1);
        g_bucket[(P[nd] - T[nd]) + pos] = e;
    }
    __syncthreads();
    {   /* insertion-sort own bucket */
        int b0 = P[t] - T[t], b1 = P[t];
        for (int i = b0 + 1; i < b1; ++i) {
            int v = g_bucket[i], j = i - 1;
            while (j >= b0 && g_bucket[j] > v) { g_bucket[j+1] = g_bucket[j]; --j; }
            g_bucket[j+1] = v;
        }
    }
}

/* ------- ZGEMM: CH[p] = NS[p]@D + W2(p)@E + bias  (level -1 = XF seed) ---- */
__global__ void __launch_bounds__(256) k_zg(int level, const int* __restrict__ ns_ptr)
{
    int S = *ns_ptr;
    int rlo, rhi;
    if (level < 0) {
        rlo = 0; rhi = (S < NN) ? S : NN;
    } else {
        int lo, hi; level_bounds(S, level, &lo, &hi);
        int PMAX = (MAXS - S + 7) >> 3;
        rlo = lo; rhi = (hi < PMAX) ? hi : PMAX;
    }
    if (rlo >= rhi) return;
    const int m0 = blockIdx.x * BM;
    if (rlo + m0 >= rhi) return;
    const int n0 = blockIdx.y * BN;

    __shared__ const __half* sP1[BM];
    __shared__ const __half* sP2[BM];
    __shared__ __half sA[BM][BK];
    __shared__ __half sB[BK][BN];
    __shared__ float  sO[BM][BN];

    const int tid = threadIdx.x;
    if (tid < BM) {
        int p = rlo + m0 + tid;
        if (p < rhi) {
            if (level < 0) {
                sP1[tid] = 0;
                sP2[tid] = g_fm_h + (size_t)p*MM;
            } else {
                sP1[tid] = g_ns_h + (size_t)p*HH;
                sP2[tid] = (p < S) ? (g_XF + (size_t)p*512 + 256)
                                   : (g_CH + (size_t)((p - S) >> 3)*512 + 256);
            }
        } else { sP1[tid] = 0; sP2[tid] = 0; }
    }
    __syncthreads();

    const int wid = tid >> 5, wr = wid & 3, wc = wid >> 2;
    wmma::fragment<wmma::accumulator,16,16,16,float> acc[2];
    wmma::fill_fragment(acc[0], 0.f);
    wmma::fill_fragment(acc[1], 0.f);
    const int ar = tid >> 2, ac = (tid & 3)*4;
    const int brw = tid >> 4, bc = (tid & 15)*4;

    for (int kt = 0; kt < 512; kt += BK) {
        const __half* base = (kt < 256) ? sP1[ar] : sP2[ar];
        uint2 v = make_uint2(0u, 0u);
        if (base) v = *(const uint2*)(base + (kt & 255) + ac);
        *(uint2*)&sA[ar][ac] = v;
        *(uint2*)&sB[brw][bc] = *(const uint2*)(g_BB + (size_t)(kt + brw)*512 + n0 + bc);
        __syncthreads();
        wmma::fragment<wmma::matrix_a,16,16,16,__half,wmma::row_major> fa;
        wmma::load_matrix_sync(fa, &sA[wr*16][0], BK);
        #pragma unroll
        for (int j = 0; j < 2; ++j) {
            wmma::fragment<wmma::matrix_b,16,16,16,__half,wmma::row_major> fb;
            wmma::load_matrix_sync(fb, &sB[0][wc*32 + j*16], BN);
            wmma::mma_sync(acc[j], fa, fb, acc[j]);
        }
        __syncthreads();
    }
    wmma::store_matrix_sync(&sO[wr*16][wc*32],      acc[0], BN, wmma::mem_row_major);
    wmma::store_matrix_sync(&sO[wr*16][wc*32 + 16], acc[1], BN, wmma::mem_row_major);
    __syncthreads();
    __half* outp = (level < 0) ? g_XF : g_CH;
    for (int idx = tid; idx < BM*BN; idx += 256) {
        int r = idx >> 6, nl = idx & 63;
        int p = rlo + m0 + r;
        if (p < rhi) {
            int n = n0 + nl;
            outp[(size_t)p*512 + n] = __float2half(sO[r][nl] + g_bias[n]);
        }
    }
}

/* ------- SEQ: per-node sequential chain within a level -------------------- */
__global__ void __launch_bounds__(256) k_seq(int level, const int* __restrict__ ns_ptr,
                                             const float* __restrict__ br)
{
    __shared__ float  s_kq[HH];
    __shared__ float2 s_part[2][128];
    __shared__ float  s_vals[HH];
    __shared__ float  s_logit[16], s_attn[HISTN];
    __shared__ int    s_i0, s_i1, s_cnt;

    int S = *ns_ptr, lo, hi;
    level_bounds(S, level, &lo, &hi);
    if (lo >= hi) return;
    const int PMAX = (MAXS - S + 7) >> 3;
    const int nd = blockIdx.x;
    const int tid = threadIdx.x;
    if (tid == 0) {
        int b0 = g_boff[nd], b1 = g_boff[nd+1];
        int i0 = b0; while (i0 < b1 && g_bucket[i0] < lo) ++i0;
        int i1 = i0; while (i1 < b1 && g_bucket[i1] < hi) ++i1;
        s_i0 = i0; s_i1 = i1; s_cnt = g_count[nd];
    }
    __syncthreads();
    const int i0 = s_i0, i1 = s_i1;
    if (i0 >= i1) return;
    int cnt = s_cnt;
    const int wid = tid >> 5, lid = tid & 31;
    const int g = tid >> 7, c = tid & 127;

    for (int i = i0; i < i1; ++i) {
        const int sstep = g_bucket[i];
        {
            const __half* kqp = (sstep < S)
                ? (g_XF + (size_t)sstep*512)
                : (g_CH + (size_t)((sstep - S) >> 3)*512);
            s_kq[tid] = __half2float(kqp[tid]);
        }
        __syncthreads();
        const int nv   = (cnt < HISTN) ? cnt : HISTN;
        const int slot = cnt % HISTN;
        #pragma unroll
        for (int pass = 0; pass < 2; ++pass) {
            int sl = wid + pass*8;
            if (sl < nv) {
                const float* hp = g_hist + ((size_t)nd*HISTN + sl)*HH;
                float p = 0.f;
                #pragma unroll
                for (int k = 0; k < 8; ++k) { int h = lid + k*32; p += hp[h]*s_kq[h]; }
                #pragma unroll
                for (int o = 16; o > 0; o >>= 1) p += __shfl_down_sync(0xffffffffu, p, o);
                if (lid == 0) s_logit[sl] = p * 0.0625f;
            }
        }
        __syncthreads();
        if (tid == 0) {
            float m = -1e30f;
            for (int k = 0; k < nv; ++k) m = fmaxf(m, s_logit[k]);
            float sum = 0.f;
            for (int k = 0; k < nv; ++k) { float e = __expf(s_logit[k]-m); s_attn[k]=e; sum+=e; }
            float inv = 1.f / sum;
            for (int k = 0; k < nv; ++k) s_attn[k] *= inv;
        }
        __syncthreads();
        {
            float v = 0.f;
            const float* hp = g_hist + (size_t)nd*HISTN*HH + tid;
            #pragma unroll 2
            for (int k = 0; k < nv; ++k) v += s_attn[k]*hp[k*HH];
            s_vals[tid] = v;
        }
        __syncthreads();
        {
            const __half2* W = (const __half2*)g_wr_h;
            float2 a = make_float2(0.f, 0.f);
            const int r0 = g*128;
            #pragma unroll 8
            for (int r = r0; r < r0+128; ++r) {
                float x = s_vals[r];
                float2 w = __half22float2(W[(size_t)r*128 + c]);
                a.x += x*w.x; a.y += x*w.y;
            }
            s_part[g][c] = a;
        }
        __syncthreads();
        if (tid < 128) {
            float2 b2 = ((const float2*)br)[tid];
            float2 r;
            r.x = s_part[0][tid].x + s_part[1][tid].x + b2.x;
            r.y = s_part[0][tid].y + s_part[1][tid].y + b2.y;
            ((float2*)(g_hist + ((size_t)nd*HISTN + slot)*HH))[tid] = r;
            if (sstep < PMAX)
                ((half2*)(g_ns_h + (size_t)sstep*HH))[tid] = __float22half2_rn(r);
        }
        ++cnt;
        __syncthreads();
    }
    if (tid == 0) g_count[nd] = cnt;
}

/* ---------------- K5: decoder + log_softmax ------------------------------- */
__global__ void k_out(const float* __restrict__ Wd, const float* __restrict__ bd,
                      float* __restrict__ out)
{
    __shared__ float s_fin[HH];
    __shared__ float s_log[PPV*OO];
    int n = blockIdx.x, t = threadIdx.x;     /* 128 threads */
    int cnt  = g_count[n];
    int slot = (cnt - 1) % HISTN;
    s_fin[t]       = g_hist[((size_t)n*HISTN + slot)*HH + t];
    s_fin[t + 128] = g_hist[((size_t)n*HISTN + slot)*HH + t + 128];
    __syncthreads();
    int p = t >> 6, o = t & 63;
    float acc = bd[p*OO + o];
    #pragma unroll 4
    for (int h = 0; h < HH; ++h) acc += s_fin[h]*Wd[((size_t)p*HH + h)*OO + o];
    s_log[t] = acc;
    __syncthreads();
    float m = -1e30f;
    for (int k = 0; k < OO; ++k) m = fmaxf(m, s_log[p*OO + k]);
    float sum = 0.f;
    for (int k = 0; k < OO; ++k) sum += expf(s_log[p*OO + k] - m);
    out[((size_t)p*NN + n)*OO + o] = acc - m - logf(sum);
}

/* -------------------------------------------------------------------------- */
extern "C" void kernel_launch(void* const* d_in, const int* in_sizes, int n_in,
                              void* d_out, int out_size)
{
    const float* xa  = (const float*)d_in[0];
    const int*   nbr = (const int*)  d_in[1];
    const float* fm  = (const float*)d_in[2];
    const float* We  = (const float*)d_in[3];
    const float* be  = (const float*)d_in[4];
    const float* Wq  = (const float*)d_in[5];
    const float* bq  = (const float*)d_in[6];
    const float* Wk  = (const float*)d_in[7];
    /* d_in[8] = bk cancels in softmax */
    const float* Wr  = (const float*)d_in[9];
    const float* br  = (const float*)d_in[10];
    const float* Wm  = (const float*)d_in[11];
    const float* bm  = (const float*)d_in[12];
    const float* Wd  = (const float*)d_in[13];
    const float* bd  = (const float*)d_in[14];
    const int*   nS  = (const int*)  d_in[15];

    k_encode<<<NN, HH>>>(xa, We, be, fm, Wm, Wr);
    k_gemmA<<<dim3(8, 4), 256>>>(Wq, Wk, Wm, bq, bm);
    k_gemmD<<<dim3(4, 8), 256>>>();
    k_graph<<<1, 512>>>(nbr, nS);
    k_zg<<<dim3(PCAP/BM, 512/BN), 256>>>(-1, nS);
    for (int lvl = 0; lvl < NLVL; ++lvl) {
        k_seq<<<NN, 256>>>(lvl, nS, br);
        k_zg<<<dim3(PCAP/BM, 512/BN), 256>>>(lvl, nS);
    }
    k_out<<<NN, 128>>>(Wd, bd, (float*)d_out);
}

// round 12
// speedup vs baseline: 1.1975x; 1.1975x over previous
#include <cuda_runtime.h>
#include <cuda_fp16.h>
#include <mma.h>
#include <math.h>

using namespace nvcuda;

#define NN    512
#define FF    128
#define HH    256
#define MM    256
#define DEGN  8
#define HISTN 10
#define OO    64
#define PPV   2
#define MAXS  (10*NN)     /* 5120 */
#define NLVL  6
#define PCAP  640
#define BM    64
#define BN    64
#define BK    16
#define NCTA  512
#define TPB2  256
#define SHSZ  26688

/* -------- persistent scratch (device globals) ----------------------------- */
__device__ float g_hist [NN*HISTN*HH];
__device__ __align__(16) __half g_XF  [NN*512];
__device__ __align__(16) __half g_CH  [PCAP*512];
__device__ __align__(16) __half g_ns_h[PCAP*HH];
__device__ __align__(16) __half g_BB  [512*512];   /* rows 0..255 = D, 256..511 = E=[A|Wm2] */
__device__ __align__(16) __half g_wm1h[HH*HH];
__device__ __align__(16) __half g_wr_h[HH*HH];
__device__ __align__(16) __half g_fm_h[NN*MM];
__device__ float g_bias [512];
__device__ int   g_bucket[MAXS];
__device__ int   g_boff  [NN+1];
__device__ int   g_count [NN];
__device__ unsigned g_barc, g_barg;

/* -------- shared overlays -------------------------------------------------- */
struct GrSh  { int sn[MAXS]; int T[NN]; int P[NN]; int cur[NN]; int chunk[16]; };
struct ZgSh  { __half sA[2][BM][BK]; __half sB[2][BK][BN]; float sO[BM][BN];
               const __half* P1[BM]; const __half* P2[BM]; };
struct SeqSh { float kq[HH]; float2 part[2][128]; float vals[HH];
               float logit[16]; float attn[16]; int i0, i1; };
struct GaSh  { float sA[16][65]; float sB[16][65]; };
struct EncSh { float sx[FF]; };
struct OutSh { float fin[HH]; float lg[PPV*OO]; };

/* ------------------------- sync helpers ---------------------------------- */
__device__ __forceinline__ unsigned ldg_acq(const unsigned* p) {
    unsigned v;
    asm volatile("ld.acquire.gpu.global.b32 %0, [%1];" : "=r"(v) : "l"(p) : "memory");
    return v;
}
__device__ __forceinline__ void stg_rel(unsigned* p, unsigned v) {
    asm volatile("st.release.gpu.global.b32 [%0], %1;" :: "l"(p), "r"(v) : "memory");
}
__device__ __forceinline__ void gbar() {
    __syncthreads();
    if (threadIdx.x == 0) {
        __threadfence();
        unsigned gen = *(volatile unsigned*)&g_barg;
        if (atomicAdd(&g_barc, 1u) == gridDim.x - 1) {
            g_barc = 0u;
            stg_rel(&g_barg, gen + 1u);
        } else {
            while (ldg_acq(&g_barg) == gen) {}
        }
    }
    __syncthreads();
}

__device__ __forceinline__ void level_bounds(int S, int level, int* plo, int* phi)
{
    int lo = 0, hi = (S < MAXS) ? S : MAXS;
    for (int l = 0; l < level; ++l) {
        lo = hi;
        int h2 = S + 8*hi;
        hi = (h2 > MAXS) ? MAXS : h2;
    }
    *plo = lo; *phi = hi;
}

/* ------------------- graph build (single CTA, 256 thr) -------------------- */
__device__ void graph_phase(char* SH, const int* __restrict__ nbr, int S, int tid)
{
    GrSh* g = (GrSh*)SH;
    for (int e = tid; e < S && e < MAXS; e += TPB2) g->sn[e] = e;
    __syncthreads();
    int known = (S < MAXS) ? S : MAXS;
    while (known < MAXS) {
        long long nx = (long long)S + 8LL*(long long)known;
        int next = (nx > MAXS) ? MAXS : (int)nx;
        for (int e = known + tid; e < next; e += TPB2) {
            int src = (e - S) >> 3;
            g->sn[e] = nbr[g->sn[src]*DEGN + ((e - S) & 7)];
        }
        __syncthreads();
        known = next;
    }
    for (int n = tid; n < NN; n += TPB2) { g->T[n] = 0; g->cur[n] = 0; }
    __syncthreads();
    for (int e = tid; e < MAXS; e += TPB2) atomicAdd(&g->T[g->sn[e]], 1);
    __syncthreads();
    /* inclusive scan of T[512] with 256 threads (2 passes of warp scans) */
    {
        const int lane = tid & 31;
        #pragma unroll
        for (int pass = 0; pass < 2; ++pass) {
            int idx = pass*TPB2 + tid;
            int v = g->T[idx];
            #pragma unroll
            for (int o = 1; o < 32; o <<= 1) {
                int u = __shfl_up_sync(0xffffffffu, v, o);
                if (lane >= o) v += u;
            }
            g->P[idx] = v;
            if (lane == 31) g->chunk[idx >> 5] = v;
        }
        __syncthreads();
        if (tid == 0) {
            int run = 0;
            for (int c2 = 0; c2 < 16; ++c2) { int t6 = g->chunk[c2]; g->chunk[c2] = run; run += t6; }
        }
        __syncthreads();
        #pragma unroll
        for (int pass = 0; pass < 2; ++pass) {
            int idx = pass*TPB2 + tid;
            g->P[idx] += g->chunk[idx >> 5];
        }
        __syncthreads();
    }
    for (int n = tid; n < NN; n += TPB2) g_boff[n] = g->P[n] - g->T[n];
    if (tid == 0) g_boff[NN] = g->P[NN-1];
    __syncthreads();
    /* bucket fill (unordered) into global */
    for (int e = tid; e < MAXS; e += TPB2) {
        int nd = g->sn[e];
        int pos = atomicAdd(&g->cur[nd], 1);
        g_bucket[(g->P[nd] - g->T[nd]) + pos] = e;
    }
    __syncthreads();
    /* copy to shared, per-node insertion sort (fast in smem), write back */
    for (int e = tid; e < MAXS; e += TPB2) g->sn[e] = g_bucket[e];
    __syncthreads();
    for (int n = tid; n < NN; n += TPB2) {
        int b0 = g->P[n] - g->T[n], b1 = g->P[n];
        for (int i = b0 + 1; i < b1; ++i) {
            int v = g->sn[i], j = i - 1;
            while (j >= b0 && g->sn[j] > v) { g->sn[j+1] = g->sn[j]; --j; }
            g->sn[j+1] = v;
        }
    }
    __syncthreads();
    for (int e = tid; e < MAXS; e += TPB2) g_bucket[e] = g->sn[e];
}

/* ------------------- gemmA tile: A=Wq@Wk^T / Wm2-pack / bias -------------- */
__device__ void gemmA_tile(char* SH, int t5,
                           const float* __restrict__ Wq, const float* __restrict__ Wk,
                           const float* __restrict__ Wm, const float* __restrict__ bq,
                           const float* __restrict__ bm, int t)
{
    const int bx = t5 >> 2, by = t5 & 3;
    __syncthreads();
    if (bx >= 4) {
        int k0 = (bx-4)*64, j0 = by*64;
        for (int i = t; i < 64*64; i += TPB2) {
            int k = k0 + (i >> 6), j = j0 + (i & 63);
            g_BB[(size_t)(256 + k)*512 + 256 + j] = __float2half(Wm[(size_t)(256 + k)*MM + j]);
        }
        if (bx == 4 && by == 0) {
            int w = t >> 5, l = t & 31;
            for (int r0 = 0; r0 < HH; r0 += 8) {
                int r = r0 + w;
                float p = 0.f;
                #pragma unroll
                for (int k = 0; k < 8; ++k) { int h = l + k*32; p += Wk[(size_t)r*HH + h]*bq[h]; }
                #pragma unroll
                for (int o = 16; o > 0; o >>= 1) p += __shfl_down_sync(0xffffffffu, p, o);
                if (l == 0) g_bias[r] = p;
            }
            g_bias[256 + t] = bm[t];
        }
        return;
    }
    GaSh* ga = (GaSh*)SH;
    const int i0 = bx*64, j0 = by*64;
    const int tx = t & 15, ty = t >> 4;
    float acc[4][4];
    #pragma unroll
    for (int a = 0; a < 4; ++a)
        #pragma unroll
        for (int b = 0; b < 4; ++b) acc[a][b] = 0.f;
    for (int kt = 0; kt < HH; kt += 16) {
        int lr = t >> 2, lh = (t & 3)*4;
        float4 va = *(const float4*)(Wq + (size_t)(i0+lr)*HH + kt + lh);
        ga->sA[lh+0][lr]=va.x; ga->sA[lh+1][lr]=va.y; ga->sA[lh+2][lr]=va.z; ga->sA[lh+3][lr]=va.w;
        float4 vb = *(const float4*)(Wk + (size_t)(j0+lr)*HH + kt + lh);
        ga->sB[lh+0][lr]=vb.x; ga->sB[lh+1][lr]=vb.y; ga->sB[lh+2][lr]=vb.z; ga->sB[lh+3][lr]=vb.w;
        __syncthreads();
        #pragma unroll
        for (int h = 0; h < 16; ++h) {
            float ra[4], rb[4];
            #pragma unroll
            for (int a = 0; a < 4; ++a) ra[a] = ga->sA[h][ty*4 + a];
            #pragma unroll
            for (int b = 0; b < 4; ++b) rb[b] = ga->sB[h][tx*4 + b];
            #pragma unroll
            for (int a = 0; a < 4; ++a)
                #pragma unroll
                for (int b = 0; b < 4; ++b) acc[a][b] += ra[a]*rb[b];
        }
        __syncthreads();
    }
    #pragma unroll
    for (int a = 0; a < 4; ++a)
        #pragma unroll
        for (int b = 0; b < 4; ++b)
            g_BB[(size_t)(256 + i0 + ty*4 + a)*512 + (j0 + tx*4 + b)] = __float2half(acc[a][b]);
}

/* ------------------- gemmD tile: D = Wm1 @ E ------------------------------ */
__device__ void gemmD_tile(char* SH, int t5, int tid)
{
    ZgSh* z = (ZgSh*)SH;
    const int m0 = (t5 >> 3) * BM, n0 = (t5 & 7) * BN;
    const int wid = tid >> 5, wr = wid & 3, wc = wid >> 2;
    const int ar = tid >> 2, ac = (tid & 3)*4;
    const int brw = tid >> 4, bc = (tid & 15)*4;
    __syncthreads();
    wmma::fragment<wmma::accumulator,16,16,16,float> acc[2];
    wmma::fill_fragment(acc[0], 0.f);
    wmma::fill_fragment(acc[1], 0.f);
    uint2 va = *(const uint2*)(g_wm1h + (size_t)(m0+ar)*HH + ac);
    uint2 vb = *(const uint2*)(g_BB + (size_t)(256 + brw)*512 + n0 + bc);
    int p = 0;
    for (int kt = 0; kt < HH; kt += BK) {
        *(uint2*)&z->sA[p][ar][ac] = va;
        *(uint2*)&z->sB[p][brw][bc] = vb;
        __syncthreads();
        if (kt + BK < HH) {
            va = *(const uint2*)(g_wm1h + (size_t)(m0+ar)*HH + kt + BK + ac);
            vb = *(const uint2*)(g_BB + (size_t)(256 + kt + BK + brw)*512 + n0 + bc);
        }
        wmma::fragment<wmma::matrix_a,16,16,16,__half,wmma::row_major> fa;
        wmma::load_matrix_sync(fa, &z->sA[p][wr*16][0], BK);
        #pragma unroll
        for (int j = 0; j < 2; ++j) {
            wmma::fragment<wmma::matrix_b,16,16,16,__half,wmma::row_major> fb;
            wmma::load_matrix_sync(fb, &z->sB[p][0][wc*32 + j*16], BN);
            wmma::mma_sync(acc[j], fa, fb, acc[j]);
        }
        p ^= 1;
    }
    wmma::store_matrix_sync(&z->sO[wr*16][wc*32],      acc[0], BN, wmma::mem_row_major);
    wmma::store_matrix_sync(&z->sO[wr*16][wc*32 + 16], acc[1], BN, wmma::mem_row_major);
    __syncthreads();
    for (int idx = tid; idx < BM*BN; idx += TPB2) {
        int r = idx >> 6, nl = idx & 63;
        g_BB[(size_t)(m0 + r)*512 + n0 + nl] = __float2half(z->sO[r][nl]);
    }
}

/* ------------------- zg tile: CH/XF = [NS|W2] @ BB + bias ----------------- */
__device__ void zg_tile(char* SH, int level, int S, int rlo, int rhi,
                        int m0, int n0, int tid)
{
    ZgSh* z = (ZgSh*)SH;
    __syncthreads();
    if (tid < BM) {
        int p = rlo + m0 + tid;
        if (p < rhi) {
            if (level < 0) {
                z->P1[tid] = 0;
                z->P2[tid] = g_fm_h + (size_t)p*MM;
            } else {
                z->P1[tid] = g_ns_h + (size_t)p*HH;
                z->P2[tid] = (p < S) ? (g_XF + (size_t)p*512 + 256)
                                     : (g_CH + (size_t)((p - S) >> 3)*512 + 256);
            }
        } else { z->P1[tid] = 0; z->P2[tid] = 0; }
    }
    __syncthreads();
    const int wid = tid >> 5, wr = wid & 3, wc = wid >> 2;
    const int ar = tid >> 2, ac = (tid & 3)*4;
    const int brw = tid >> 4, bc = (tid & 15)*4;
    wmma::fragment<wmma::accumulator,16,16,16,float> acc[2];
    wmma::fill_fragment(acc[0], 0.f);
    wmma::fill_fragment(acc[1], 0.f);
    const __half* base0 = z->P1[ar];
    uint2 va = base0 ? *(const uint2*)(base0 + ac) : make_uint2(0u,0u);
    uint2 vb = *(const uint2*)(g_BB + (size_t)brw*512 + n0 + bc);
    int p = 0;
    for (int kt = 0; kt < 512; kt += BK) {
        *(uint2*)&z->sA[p][ar][ac] = va;
        *(uint2*)&z->sB[p][brw][bc] = vb;
        __syncthreads();
        int kn = kt + BK;
        if (kn < 512) {
            const __half* base = (kn < 256) ? z->P1[ar] : z->P2[ar];
            va = base ? *(const uint2*)(base + (kn & 255) + ac) : make_uint2(0u,0u);
            vb = *(const uint2*)(g_BB + (size_t)(kn + brw)*512 + n0 + bc);
        }
        wmma::fragment<wmma::matrix_a,16,16,16,__half,wmma::row_major> fa;
        wmma::load_matrix_sync(fa, &z->sA[p][wr*16][0], BK);
        #pragma unroll
        for (int j = 0; j < 2; ++j) {
            wmma::fragment<wmma::matrix_b,16,16,16,__half,wmma::row_major> fb;
            wmma::load_matrix_sync(fb, &z->sB[p][0][wc*32 + j*16], BN);
            wmma::mma_sync(acc[j], fa, fb, acc[j]);
        }
        p ^= 1;
    }
    wmma::store_matrix_sync(&z->sO[wr*16][wc*32],      acc[0], BN, wmma::mem_row_major);
    wmma::store_matrix_sync(&z->sO[wr*16][wc*32 + 16], acc[1], BN, wmma::mem_row_major);
    __syncthreads();
    __half* outp = (level < 0) ? g_XF : g_CH;
    for (int idx = tid; idx < BM*BN; idx += TPB2) {
        int r = idx >> 6, nl = idx & 63;
        int pp = rlo + m0 + r;
        if (pp < rhi) {
            int n = n0 + nl;
            outp[(size_t)pp*512 + n] = __float2half(z->sO[r][nl] + g_bias[n]);
        }
    }
}

__device__ void zg_phase(char* SH, int level, int S, int tid, int cta)
{
    int rlo, rhi;
    if (level < 0) { rlo = 0; rhi = (S < NN) ? S : NN; }
    else {
        int lo, hi; level_bounds(S, level, &lo, &hi);
        int PM = (MAXS - S + 7) >> 3;
        rlo = lo; rhi = (hi < PM) ? hi : PM;
    }
    if (rlo >= rhi) return;
    int rows = rhi - rlo, RT = (rows + BM - 1) / BM;
    for (int t5 = cta; t5 < RT*8; t5 += NCTA)
        zg_tile(SH, level, S, rlo, rhi, (t5 >> 3)*BM, (t5 & 7)*BN, tid);
}

/* ------------------- seq: per-node chain within level --------------------- */
__device__ void seq_phase(char* SH, int lo, int hi, int S,
                          const float* __restrict__ br, int tid, int cta)
{
    if (cta >= NN) return;
    SeqSh* q = (SeqSh*)SH;
    const int nd = cta;
    const int PM = (MAXS - S + 7) >> 3;
    if (tid == 0) {
        int b0 = g_boff[nd], b1 = g_boff[nd+1];
        int i0 = b0; while (i0 < b1 && g_bucket[i0] < lo) ++i0;
        int i1 = i0; while (i1 < b1 && g_bucket[i1] < hi) ++i1;
        q->i0 = i0; q->i1 = i1;
    }
    __syncthreads();
    const int i0 = q->i0, i1 = q->i1;
    if (i0 >= i1) return;
    int cnt = g_count[nd];
    const int wid = tid >> 5, lid = tid & 31;
    const int g = tid >> 7, c = tid & 127;

    for (int i = i0; i < i1; ++i) {
        const int sstep = g_bucket[i];
        {
            const __half* kqp = (sstep < S)
                ? (g_XF + (size_t)sstep*512)
                : (g_CH + (size_t)((sstep - S) >> 3)*512);
            q->kq[tid] = __half2float(kqp[tid]);
        }
        __syncthreads();
        const int nv   = (cnt < HISTN) ? cnt : HISTN;
        const int slot = cnt % HISTN;
        #pragma unroll
        for (int pass = 0; pass < 2; ++pass) {
            int sl = wid + pass*8;
            if (sl < nv) {
                const float* hp = g_hist + ((size_t)nd*HISTN + sl)*HH;
                float p = 0.f;
                #pragma unroll
                for (int k = 0; k < 8; ++k) { int h = lid + k*32; p += hp[h]*q->kq[h]; }
                #pragma unroll
                for (int o = 16; o > 0; o >>= 1) p += __shfl_down_sync(0xffffffffu, p, o);
                if (lid == 0) q->logit[sl] = p * 0.0625f;
            }
        }
        __syncthreads();
        if (tid == 0) {
            float m = -1e30f;
            for (int k = 0; k < nv; ++k) m = fmaxf(m, q->logit[k]);
            float sum = 0.f;
            for (int k = 0; k < nv; ++k) { float e = __expf(q->logit[k]-m); q->attn[k]=e; sum+=e; }
            float inv = 1.f / sum;
            for (int k = 0; k < nv; ++k) q->attn[k] *= inv;
        }
        __syncthreads();
        {
            float v = 0.f;
            const float* hp = g_hist + (size_t)nd*HISTN*HH + tid;
            #pragma unroll 2
            for (int k = 0; k < nv; ++k) v += q->attn[k]*hp[k*HH];
            q->vals[tid] = v;
        }
        __syncthreads();
        {
            const __half2* W = (const __half2*)g_wr_h;
            float2 a = make_float2(0.f, 0.f);
            const int r0 = g*128;
            #pragma unroll 8
            for (int r = r0; r < r0+128; ++r) {
                float x = q->vals[r];
                float2 w = __half22float2(W[(size_t)r*128 + c]);
                a.x += x*w.x; a.y += x*w.y;
            }
            q->part[g][c] = a;
        }
        __syncthreads();
        if (tid < 128) {
            float2 b2 = ((const float2*)br)[tid];
            float2 r;
            r.x = q->part[0][tid].x + q->part[1][tid].x + b2.x;
            r.y = q->part[0][tid].y + q->part[1][tid].y + b2.y;
            ((float2*)(g_hist + ((size_t)nd*HISTN + slot)*HH))[tid] = r;
            if (sstep < PM)
                ((half2*)(g_ns_h + (size_t)sstep*HH))[tid] = __float22half2_rn(r);
        }
        ++cnt;
        __syncthreads();
    }
    if (tid == 0) g_count[nd] = cnt;
}

/* ------------------- mega kernel ------------------------------------------ */
__global__ void __launch_bounds__(TPB2, 4)
k_mega(const float* __restrict__ xa, const int* __restrict__ nbr,
       const float* __restrict__ fm,
       const float* __restrict__ We, const float* __restrict__ be,
       const float* __restrict__ Wq, const float* __restrict__ bq,
       const float* __restrict__ Wk,
       const float* __restrict__ Wr, const float* __restrict__ br,
       const float* __restrict__ Wm, const float* __restrict__ bm,
       const float* __restrict__ Wd, const float* __restrict__ bd,
       const int* __restrict__ nS, float* __restrict__ out)
{
    __shared__ __align__(16) char SH[SHSZ];
    const int cta = blockIdx.x, tid = threadIdx.x;
    const int S = *nS;

    /* ---- P0: graph (CTA 511) || encode + packs + gemmA (others) ---- */
    if (cta == NCTA-1) {
        graph_phase(SH, nbr, S, tid);
    } else {
        EncSh* es = (EncSh*)SH;
        for (int n = cta; n < NN; n += NCTA-1) {
            if (tid < FF) es->sx[tid] = xa[n*FF + tid];
            __syncthreads();
            float acc = be[tid];
            #pragma unroll 4
            for (int f = 0; f < FF; ++f) acc += es->sx[f] * We[f*HH + tid];
            g_hist[((size_t)n*HISTN + 0)*HH + tid] = acc;
            g_fm_h[(size_t)n*MM + tid] = __float2half(fm[(size_t)n*MM + tid]);
            if (tid == 0) g_count[n] = 1;
            __syncthreads();
        }
        for (int r = cta; r < HH; r += NCTA-1) {
            g_wm1h[(size_t)r*MM + tid] = __float2half(Wm[(size_t)r*MM + tid]);
            float s = Wr[r*HH + tid] + Wr[(HH + r)*HH + tid]
                    + Wr[(2*HH + r)*HH + tid] + Wr[(3*HH + r)*HH + tid];
            g_wr_h[r*HH + tid] = __float2half(s);
        }
        for (int t5 = cta; t5 < 32; t5 += NCTA-1)
            gemmA_tile(SH, t5, Wq, Wk, Wm, bq, bm, tid);
    }
    gbar();
    /* ---- P1: D = Wm1 @ E ---- */
    for (int t5 = cta; t5 < 32; t5 += NCTA) gemmD_tile(SH, t5, tid);
    gbar();
    /* ---- P2: XF seed ---- */
    zg_phase(SH, -1, S, tid, cta);
    gbar();
    /* ---- levels ---- */
    for (int lvl = 0; lvl < NLVL; ++lvl) {
        int lo, hi; level_bounds(S, lvl, &lo, &hi);
        if (lo >= hi) break;
        seq_phase(SH, lo, hi, S, br, tid, cta);
        gbar();
        zg_phase(SH, lvl, S, tid, cta);
        gbar();
    }
    /* ---- out: decoder + log_softmax ---- */
    if (cta < NN) {
        OutSh* o = (OutSh*)SH;
        int cnt  = g_count[cta];
        int slot = (cnt - 1) % HISTN;
        o->fin[tid] = g_hist[((size_t)cta*HISTN + slot)*HH + tid];
        __syncthreads();
        if (tid < PPV*OO) {
            int p = tid >> 6, qo = tid & 63;
            float acc = bd[p*OO + qo];
            #pragma unroll 4
            for (int h = 0; h < HH; ++h) acc += o->fin[h]*Wd[((size_t)p*HH + h)*OO + qo];
            o->lg[tid] = acc;
        }
        __syncthreads();
        if (tid < PPV*OO) {
            int p = tid >> 6, qo = tid & 63;
            float m = -1e30f;
            for (int k = 0; k < OO; ++k) m = fmaxf(m, o->lg[p*OO + k]);
            float sum = 0.f;
            for (int k = 0; k < OO; ++k) sum += expf(o->lg[p*OO + k] - m);
            out[((size_t)p*NN + cta)*OO + qo] = o->lg[tid] - m - logf(sum);
        }
    }
}

/* -------------------------------------------------------------------------- */
extern "C" void kernel_launch(void* const* d_in, const int* in_sizes, int n_in,
                              void* d_out, int out_size)
{
    const float* xa  = (const float*)d_in[0];
    const int*   nbr = (const int*)  d_in[1];
    const float* fm  = (const float*)d_in[2];
    const float* We  = (const float*)d_in[3];
    const float* be  = (const float*)d_in[4];
    const float* Wq  = (const float*)d_in[5];
    const float* bq  = (const float*)d_in[6];
    const float* Wk  = (const float*)d_in[7];
    /* d_in[8] = bk cancels in softmax */
    const float* Wr  = (const float*)d_in[9];
    const float* br  = (const float*)d_in[10];
    const float* Wm  = (const float*)d_in[11];
    const float* bm  = (const float*)d_in[12];
    const float* Wd  = (const float*)d_in[13];
    const float* bd  = (const float*)d_in[14];
    const int*   nS  = (const int*)  d_in[15];

    k_mega<<<NCTA, TPB2>>>(xa, nbr, fm, We, be, Wq, bq, Wk, Wr, br,
                           Wm, bm, Wd, bd, nS, (float*)d_out);
}

// round 13
// speedup vs baseline: 1.2023x; 1.0040x over previous
#include <cuda_runtime.h>
#include <cuda_fp16.h>
#include <mma.h>
#include <math.h>

using namespace nvcuda;

#define NN    512
#define FF    128
#define HH    256
#define MM    256
#define DEGN  8
#define HISTN 10
#define OO    64
#define PPV   2
#define MAXS  (10*NN)     /* 5120 */
#define NLVL  6
#define PCAP  640
#define BM    64
#define BN    64
#define BK    16
#define NCTA  512
#define TPB2  256
#define SHSZ  26688
#define NGRP  16          /* barrier groups (32 CTAs each) */

/* -------- persistent scratch (device globals) ----------------------------- */
__device__ float g_hist [NN*HISTN*HH];
__device__ __align__(16) __half g_XF  [NN*512];
__device__ __align__(16) __half g_CH  [PCAP*512];
__device__ __align__(16) __half g_ns_h[PCAP*HH];
__device__ __align__(16) __half g_BB  [512*512];   /* rows 0..255 = D, 256..511 = E=[A|Wm2] */
__device__ __align__(16) __half g_wm1h[HH*HH];
__device__ __align__(16) __half g_wr_h[HH*HH];
__device__ __align__(16) __half g_fm_h[NN*MM];
__device__ float g_bias [512];
__device__ int   g_bucket[MAXS];
__device__ int   g_boff  [NN+1];
__device__ int   g_count [NN];
__device__ __align__(128) unsigned g_grpc[NGRP][32];   /* 128B-padded group counters */
__device__ unsigned g_rootc;
__device__ unsigned g_gen;

/* -------- shared overlays -------------------------------------------------- */
struct GrSh  { int sn[MAXS]; int T[NN]; int P[NN]; int cur[NN]; int chunk[16]; };
struct ZgSh  { __half sA[2][BM][BK]; __half sB[2][BK][BN]; float sO[BM][BN];
               const __half* P1[BM]; const __half* P2[BM]; };
struct SeqSh { float hist[HISTN][HH]; float kq[HH]; float2 part[2][128];
               float vals[HH]; float logit[16]; float attn[16]; int i0, i1; };
struct GaSh  { float sA[16][65]; float sB[16][65]; };
struct EncSh { float sx[FF]; };
struct OutSh { float fin[HH]; float lg[PPV*OO]; };

/* ------------------------- sync helpers ---------------------------------- */
__device__ __forceinline__ unsigned ldg_acq(const unsigned* p) {
    unsigned v;
    asm volatile("ld.acquire.gpu.global.b32 %0, [%1];" : "=r"(v) : "l"(p) : "memory");
    return v;
}
__device__ __forceinline__ void stg_rel(unsigned* p, unsigned v) {
    asm volatile("st.release.gpu.global.b32 [%0], %1;" :: "l"(p), "r"(v) : "memory");
}
/* tree barrier: 32-wide group arrival -> 16-wide root -> flat flag release */
__device__ __forceinline__ void gbar(int cta, unsigned target) {
    __syncthreads();
    if (threadIdx.x == 0) {
        __threadfence();
        int grp = cta >> 5;
        if (atomicAdd(&g_grpc[grp][0], 1u) == 31u) {
            *(volatile unsigned*)&g_grpc[grp][0] = 0u;
            __threadfence();
            if (atomicAdd(&g_rootc, 1u) == (unsigned)(NGRP-1)) {
                *(volatile unsigned*)&g_rootc = 0u;
                stg_rel(&g_gen, target);
            }
        }
        while ((int)(ldg_acq(&g_gen) - target) < 0) {}
    }
    __syncthreads();
}

__device__ __forceinline__ void level_bounds(int S, int level, int* plo, int* phi)
{
    int lo = 0, hi = (S < MAXS) ? S : MAXS;
    for (int l = 0; l < level; ++l) {
        lo = hi;
        int h2 = S + 8*hi;
        hi = (h2 > MAXS) ? MAXS : h2;
    }
    *plo = lo; *phi = hi;
}

/* ------------------- graph build (single CTA, 256 thr) -------------------- */
__device__ void graph_phase(char* SH, const int* __restrict__ nbr, int S, int tid)
{
    GrSh* g = (GrSh*)SH;
    for (int e = tid; e < S && e < MAXS; e += TPB2) g->sn[e] = e;
    __syncthreads();
    int known = (S < MAXS) ? S : MAXS;
    while (known < MAXS) {
        long long nx = (long long)S + 8LL*(long long)known;
        int next = (nx > MAXS) ? MAXS : (int)nx;
        for (int e = known + tid; e < next; e += TPB2) {
            int src = (e - S) >> 3;
            g->sn[e] = nbr[g->sn[src]*DEGN + ((e - S) & 7)];
        }
        __syncthreads();
        known = next;
    }
    for (int n = tid; n < NN; n += TPB2) { g->T[n] = 0; g->cur[n] = 0; }
    __syncthreads();
    for (int e = tid; e < MAXS; e += TPB2) atomicAdd(&g->T[g->sn[e]], 1);
    __syncthreads();
    {
        const int lane = tid & 31;
        #pragma unroll
        for (int pass = 0; pass < 2; ++pass) {
            int idx = pass*TPB2 + tid;
            int v = g->T[idx];
            #pragma unroll
            for (int o = 1; o < 32; o <<= 1) {
                int u = __shfl_up_sync(0xffffffffu, v, o);
                if (lane >= o) v += u;
            }
            g->P[idx] = v;
            if (lane == 31) g->chunk[idx >> 5] = v;
        }
        __syncthreads();
        if (tid == 0) {
            int run = 0;
            for (int c2 = 0; c2 < 16; ++c2) { int t6 = g->chunk[c2]; g->chunk[c2] = run; run += t6; }
        }
        __syncthreads();
        #pragma unroll
        for (int pass = 0; pass < 2; ++pass) {
            int idx = pass*TPB2 + tid;
            g->P[idx] += g->chunk[idx >> 5];
        }
        __syncthreads();
    }
    for (int n = tid; n < NN; n += TPB2) g_boff[n] = g->P[n] - g->T[n];
    if (tid == 0) g_boff[NN] = g->P[NN-1];
    __syncthreads();
    for (int e = tid; e < MAXS; e += TPB2) {
        int nd = g->sn[e];
        int pos = atomicAdd(&g->cur[nd], 1);
        g_bucket[(g->P[nd] - g->T[nd]) + pos] = e;
    }
    __syncthreads();
    for (int e = tid; e < MAXS; e += TPB2) g->sn[e] = g_bucket[e];
    __syncthreads();
    for (int n = tid; n < NN; n += TPB2) {
        int b0 = g->P[n] - g->T[n], b1 = g->P[n];
        for (int i = b0 + 1; i < b1; ++i) {
            int v = g->sn[i], j = i - 1;
            while (j >= b0 && g->sn[j] > v) { g->sn[j+1] = g->sn[j]; --j; }
            g->sn[j+1] = v;
        }
    }
    __syncthreads();
    for (int e = tid; e < MAXS; e += TPB2) g_bucket[e] = g->sn[e];
}

/* ------------------- gemmA tile: A=Wq@Wk^T / Wm2-pack / bias -------------- */
__device__ void gemmA_tile(char* SH, int t5,
                           const float* __restrict__ Wq, const float* __restrict__ Wk,
                           const float* __restrict__ Wm, const float* __restrict__ bq,
                           const float* __restrict__ bm, int t)
{
    const int bx = t5 >> 2, by = t5 & 3;
    __syncthreads();
    if (bx >= 4) {
        int k0 = (bx-4)*64, j0 = by*64;
        for (int i = t; i < 64*64; i += TPB2) {
            int k = k0 + (i >> 6), j = j0 + (i & 63);
            g_BB[(size_t)(256 + k)*512 + 256 + j] = __float2half(Wm[(size_t)(256 + k)*MM + j]);
        }
        if (bx == 4 && by == 0) {
            int w = t >> 5, l = t & 31;
            for (int r0 = 0; r0 < HH; r0 += 8) {
                int r = r0 + w;
                float p = 0.f;
                #pragma unroll
                for (int k = 0; k < 8; ++k) { int h = l + k*32; p += Wk[(size_t)r*HH + h]*bq[h]; }
                #pragma unroll
                for (int o = 16; o > 0; o >>= 1) p += __shfl_down_sync(0xffffffffu, p, o);
                if (l == 0) g_bias[r] = p;
            }
            g_bias[256 + t] = bm[t];
        }
        return;
    }
    GaSh* ga = (GaSh*)SH;
    const int i0 = bx*64, j0 = by*64;
    const int tx = t & 15, ty = t >> 4;
    float acc[4][4];
    #pragma unroll
    for (int a = 0; a < 4; ++a)
        #pragma unroll
        for (int b = 0; b < 4; ++b) acc[a][b] = 0.f;
    for (int kt = 0; kt < HH; kt += 16) {
        int lr = t >> 2, lh = (t & 3)*4;
        float4 va = *(const float4*)(Wq + (size_t)(i0+lr)*HH + kt + lh);
        ga->sA[lh+0][lr]=va.x; ga->sA[lh+1][lr]=va.y; ga->sA[lh+2][lr]=va.z; ga->sA[lh+3][lr]=va.w;
        float4 vb = *(const float4*)(Wk + (size_t)(j0+lr)*HH + kt + lh);
        ga->sB[lh+0][lr]=vb.x; ga->sB[lh+1][lr]=vb.y; ga->sB[lh+2][lr]=vb.z; ga->sB[lh+3][lr]=vb.w;
        __syncthreads();
        #pragma unroll
        for (int h = 0; h < 16; ++h) {
            float ra[4], rb[4];
            #pragma unroll
            for (int a = 0; a < 4; ++a) ra[a] = ga->sA[h][ty*4 + a];
            #pragma unroll
            for (int b = 0; b < 4; ++b) rb[b] = ga->sB[h][tx*4 + b];
            #pragma unroll
            for (int a = 0; a < 4; ++a)
                #pragma unroll
                for (int b = 0; b < 4; ++b) acc[a][b] += ra[a]*rb[b];
        }
        __syncthreads();
    }
    #pragma unroll
    for (int a = 0; a < 4; ++a)
        #pragma unroll
        for (int b = 0; b < 4; ++b)
            g_BB[(size_t)(256 + i0 + ty*4 + a)*512 + (j0 + tx*4 + b)] = __float2half(acc[a][b]);
}

/* ------------------- gemmD tile: D = Wm1 @ E (2-deep prefetch) ------------ */
__device__ void gemmD_tile(char* SH, int t5, int tid)
{
    ZgSh* z = (ZgSh*)SH;
    const int m0 = (t5 >> 3) * BM, n0 = (t5 & 7) * BN;
    const int wid = tid >> 5, wr = wid & 3, wc = wid >> 2;
    const int ar = tid >> 2, ac = (tid & 3)*4;
    const int brw = tid >> 4, bc = (tid & 15)*4;
    const int KT = HH / BK;    /* 16 */
    __syncthreads();
    wmma::fragment<wmma::accumulator,16,16,16,float> acc[2];
    wmma::fill_fragment(acc[0], 0.f);
    wmma::fill_fragment(acc[1], 0.f);
    #define LDA_D(k) (*(const uint2*)(g_wm1h + (size_t)(m0+ar)*HH + (k)*BK + ac))
    #define LDB_D(k) (*(const uint2*)(g_BB + (size_t)(256 + (k)*BK + brw)*512 + n0 + bc))
    uint2 rA[2], rB[2];
    {
        uint2 tA = LDA_D(0), tB = LDB_D(0);
        *(uint2*)&z->sA[0][ar][ac] = tA;
        *(uint2*)&z->sB[0][brw][bc] = tB;
        rA[1] = LDA_D(1); rB[1] = LDB_D(1);
        rA[0] = LDA_D(2); rB[0] = LDB_D(2);
    }
    __syncthreads();
    for (int k = 0; k < KT; ++k) {
        const int p = k & 1, q = p ^ 1;
        if (k + 1 < KT) {
            *(uint2*)&z->sA[q][ar][ac] = rA[q];
            *(uint2*)&z->sB[q][brw][bc] = rB[q];
        }
        if (k + 3 < KT) { rA[q] = LDA_D(k+3); rB[q] = LDB_D(k+3); }
        wmma::fragment<wmma::matrix_a,16,16,16,__half,wmma::row_major> fa;
        wmma::load_matrix_sync(fa, &z->sA[p][wr*16][0], BK);
        #pragma unroll
        for (int j = 0; j < 2; ++j) {
            wmma::fragment<wmma::matrix_b,16,16,16,__half,wmma::row_major> fb;
            wmma::load_matrix_sync(fb, &z->sB[p][0][wc*32 + j*16], BN);
            wmma::mma_sync(acc[j], fa, fb, acc[j]);
        }
        __syncthreads();
    }
    #undef LDA_D
    #undef LDB_D
    wmma::store_matrix_sync(&z->sO[wr*16][wc*32],      acc[0], BN, wmma::mem_row_major);
    wmma::store_matrix_sync(&z->sO[wr*16][wc*32 + 16], acc[1], BN, wmma::mem_row_major);
    __syncthreads();
    for (int idx = tid; idx < BM*BN; idx += TPB2) {
        int r = idx >> 6, nl = idx & 63;
        g_BB[(size_t)(m0 + r)*512 + n0 + nl] = __float2half(z->sO[r][nl]);
    }
}

/* ------------------- zg tile: CH/XF = [NS|W2] @ BB + bias (2-deep) -------- */
__device__ void zg_tile(char* SH, int level, int S, int rlo, int rhi,
                        int m0, int n0, int tid)
{
    ZgSh* z = (ZgSh*)SH;
    __syncthreads();
    if (tid < BM) {
        int p = rlo + m0 + tid;
        if (p < rhi) {
            if (level < 0) {
                z->P1[tid] = 0;
                z->P2[tid] = g_fm_h + (size_t)p*MM;
            } else {
                z->P1[tid] = g_ns_h + (size_t)p*HH;
                z->P2[tid] = (p < S) ? (g_XF + (size_t)p*512 + 256)
                                     : (g_CH + (size_t)((p - S) >> 3)*512 + 256);
            }
        } else { z->P1[tid] = 0; z->P2[tid] = 0; }
    }
    __syncthreads();
    const int wid = tid >> 5, wr = wid & 3, wc = wid >> 2;
    const int ar = tid >> 2, ac = (tid & 3)*4;
    const int brw = tid >> 4, bc = (tid & 15)*4;
    const __half* p1 = z->P1[ar];
    const __half* p2 = z->P2[ar];
    wmma::fragment<wmma::accumulator,16,16,16,float> acc[2];
    wmma::fill_fragment(acc[0], 0.f);
    wmma::fill_fragment(acc[1], 0.f);
    const int KT = 512 / BK;   /* 32 */
    #define LDA_Z(k) ({ int kt = (k)*BK; const __half* b_ = (kt < 256) ? p1 : p2; \
                        b_ ? *(const uint2*)(b_ + (kt & 255) + ac) : make_uint2(0u,0u); })
    #define LDB_Z(k) (*(const uint2*)(g_BB + (size_t)((k)*BK + brw)*512 + n0 + bc))
    uint2 rA[2], rB[2];
    {
        uint2 tA = LDA_Z(0), tB = LDB_Z(0);
        *(uint2*)&z->sA[0][ar][ac] = tA;
        *(uint2*)&z->sB[0][brw][bc] = tB;
        rA[1] = LDA_Z(1); rB[1] = LDB_Z(1);
        rA[0] = LDA_Z(2); rB[0] = LDB_Z(2);
    }
    __syncthreads();
    for (int k = 0; k < KT; ++k) {
        const int p = k & 1, q = p ^ 1;
        if (k + 1 < KT) {
            *(uint2*)&z->sA[q][ar][ac] = rA[q];
            *(uint2*)&z->sB[q][brw][bc] = rB[q];
        }
        if (k + 3 < KT) { rA[q] = LDA_Z(k+3); rB[q] = LDB_Z(k+3); }
        wmma::fragment<wmma::matrix_a,16,16,16,__half,wmma::row_major> fa;
        wmma::load_matrix_sync(fa, &z->sA[p][wr*16][0], BK);
        #pragma unroll
        for (int j = 0; j < 2; ++j) {
            wmma::fragment<wmma::matrix_b,16,16,16,__half,wmma::row_major> fb;
            wmma::load_matrix_sync(fb, &z->sB[p][0][wc*32 + j*16], BN);
            wmma::mma_sync(acc[j], fa, fb, acc[j]);
        }
        __syncthreads();
    }
    #undef LDA_Z
    #undef LDB_Z
    wmma::store_matrix_sync(&z->sO[wr*16][wc*32],      acc[0], BN, wmma::mem_row_major);
    wmma::store_matrix_sync(&z->sO[wr*16][wc*32 + 16], acc[1], BN, wmma::mem_row_major);
    __syncthreads();
    __half* outp = (level < 0) ? g_XF : g_CH;
    for (int idx = tid; idx < BM*BN; idx += TPB2) {
        int r = idx >> 6, nl = idx & 63;
        int pp = rlo + m0 + r;
        if (pp < rhi) {
            int n = n0 + nl;
            outp[(size_t)pp*512 + n] = __float2half(z->sO[r][nl] + g_bias[n]);
        }
    }
}

__device__ void zg_phase(char* SH, int level, int S, int tid, int cta)
{
    int rlo, rhi;
    if (level < 0) { rlo = 0; rhi = (S < NN) ? S : NN; }
    else {
        int lo, hi; level_bounds(S, level, &lo, &hi);
        int PM = (MAXS - S + 7) >> 3;
        rlo = lo; rhi = (hi < PM) ? hi : PM;
    }
    if (rlo >= rhi) return;
    int rows = rhi - rlo, RT = (rows + BM - 1) / BM;
    for (int t5 = cta; t5 < RT*8; t5 += NCTA)
        zg_tile(SH, level, S, rlo, rhi, (t5 >> 3)*BM, (t5 & 7)*BN, tid);
}

/* ------------------- seq: per-node chain within level (smem hist) --------- */
__device__ void seq_phase(char* SH, int lo, int hi, int S,
                          const float* __restrict__ br, int tid, int cta)
{
    if (cta >= NN) return;
    SeqSh* q = (SeqSh*)SH;
    const int nd = cta;
    const int PM = (MAXS - S + 7) >> 3;
    if (tid == 0) {
        int b0 = g_boff[nd], b1 = g_boff[nd+1];
        int i0 = b0; while (i0 < b1 && g_bucket[i0] < lo) ++i0;
        int i1 = i0; while (i1 < b1 && g_bucket[i1] < hi) ++i1;
        q->i0 = i0; q->i1 = i1;
    }
    __syncthreads();
    const int i0 = q->i0, i1 = q->i1;
    if (i0 >= i1) return;
    int cnt = g_count[nd];
    const int wid = tid >> 5, lid = tid & 31;
    const int g = tid >> 7, c = tid & 127;

    /* load node hist ring into smem once per level */
    #pragma unroll
    for (int r = 0; r < HISTN; ++r)
        q->hist[r][tid] = g_hist[((size_t)nd*HISTN + r)*HH + tid];
    __syncthreads();

    for (int i = i0; i < i1; ++i) {
        const int sstep = g_bucket[i];
        {
            const __half* kqp = (sstep < S)
                ? (g_XF + (size_t)sstep*512)
                : (g_CH + (size_t)((sstep - S) >> 3)*512);
            q->kq[tid] = __half2float(kqp[tid]);
        }
        __syncthreads();
        const int nv   = (cnt < HISTN) ? cnt : HISTN;
        const int slot = cnt % HISTN;
        #pragma unroll
        for (int pass = 0; pass < 2; ++pass) {
            int sl = wid + pass*8;
            if (sl < nv) {
                const float* hp = q->hist[sl];
                float p = 0.f;
                #pragma unroll
                for (int k = 0; k < 8; ++k) { int h = lid + k*32; p += hp[h]*q->kq[h]; }
                #pragma unroll
                for (int o = 16; o > 0; o >>= 1) p += __shfl_down_sync(0xffffffffu, p, o);
                if (lid == 0) q->logit[sl] = p * 0.0625f;
            }
        }
        __syncthreads();
        if (tid == 0) {
            float m = -1e30f;
            for (int k = 0; k < nv; ++k) m = fmaxf(m, q->logit[k]);
            float sum = 0.f;
            for (int k = 0; k < nv; ++k) { float e = __expf(q->logit[k]-m); q->attn[k]=e; sum+=e; }
            float inv = 1.f / sum;
            for (int k = 0; k < nv; ++k) q->attn[k] *= inv;
        }
        __syncthreads();
        {
            float v = 0.f;
            #pragma unroll 2
            for (int k = 0; k < nv; ++k) v += q->attn[k]*q->hist[k][tid];
            q->vals[tid] = v;
        }
        __syncthreads();
        {
            const __half2* W = (const __half2*)g_wr_h;
            float2 a = make_float2(0.f, 0.f);
            const int r0 = g*128;
            #pragma unroll 8
            for (int r = r0; r < r0+128; ++r) {
                float x = q->vals[r];
                float2 w = __half22float2(W[(size_t)r*128 + c]);
                a.x += x*w.x; a.y += x*w.y;
            }
            q->part[g][c] = a;
        }
        __syncthreads();
        if (tid < 128) {
            float2 b2 = ((const float2*)br)[tid];
            float2 r;
            r.x = q->part[0][tid].x + q->part[1][tid].x + b2.x;
            r.y = q->part[0][tid].y + q->part[1][tid].y + b2.y;
            ((float2*)q->hist[slot])[tid] = r;
            ((float2*)(g_hist + ((size_t)nd*HISTN + slot)*HH))[tid] = r;
            if (sstep < PM)
                ((half2*)(g_ns_h + (size_t)sstep*HH))[tid] = __float22half2_rn(r);
        }
        ++cnt;
        __syncthreads();
    }
    if (tid == 0) g_count[nd] = cnt;
}

/* ------------------- mega kernel ------------------------------------------ */
__global__ void __launch_bounds__(TPB2, 4)
k_mega(const float* __restrict__ xa, const int* __restrict__ nbr,
       const float* __restrict__ fm,
       const float* __restrict__ We, const float* __restrict__ be,
       const float* __restrict__ Wq, const float* __restrict__ bq,
       const float* __restrict__ Wk,
       const float* __restrict__ Wr, const float* __restrict__ br,
       const float* __restrict__ Wm, const float* __restrict__ bm,
       const float* __restrict__ Wd, const float* __restrict__ bd,
       const int* __restrict__ nS, float* __restrict__ out)
{
    __shared__ __align__(16) char SH[SHSZ];
    __shared__ unsigned sh_base;
    const int cta = blockIdx.x, tid = threadIdx.x;
    const int S = *nS;

    if (tid == 0) sh_base = *(volatile unsigned*)&g_gen;
    __syncthreads();
    unsigned bt = sh_base;

    /* ---- P0: graph (CTA 511) || encode + packs + gemmA (others) ---- */
    if (cta == NCTA-1) {
        graph_phase(SH, nbr, S, tid);
    } else {
        EncSh* es = (EncSh*)SH;
        for (int n = cta; n < NN; n += NCTA-1) {
            if (tid < FF) es->sx[tid] = xa[n*FF + tid];
            __syncthreads();
            float acc = be[tid];
            #pragma unroll 4
            for (int f = 0; f < FF; ++f) acc += es->sx[f] * We[f*HH + tid];
            g_hist[((size_t)n*HISTN + 0)*HH + tid] = acc;
            g_fm_h[(size_t)n*MM + tid] = __float2half(fm[(size_t)n*MM + tid]);
            if (tid == 0) g_count[n] = 1;
            __syncthreads();
        }
        for (int r = cta; r < HH; r += NCTA-1) {
            g_wm1h[(size_t)r*MM + tid] = __float2half(Wm[(size_t)r*MM + tid]);
            float s = Wr[r*HH + tid] + Wr[(HH + r)*HH + tid]
                    + Wr[(2*HH + r)*HH + tid] + Wr[(3*HH + r)*HH + tid];
            g_wr_h[r*HH + tid] = __float2half(s);
        }
        for (int t5 = cta; t5 < 32; t5 += NCTA-1)
            gemmA_tile(SH, t5, Wq, Wk, Wm, bq, bm, tid);
    }
    gbar(cta, ++bt);
    /* ---- P1: D = Wm1 @ E ---- */
    for (int t5 = cta; t5 < 32; t5 += NCTA) gemmD_tile(SH, t5, tid);
    gbar(cta, ++bt);
    /* ---- P2: XF seed ---- */
    zg_phase(SH, -1, S, tid, cta);
    gbar(cta, ++bt);
    /* ---- levels ---- */
    for (int lvl = 0; lvl < NLVL; ++lvl) {
        int lo, hi; level_bounds(S, lvl, &lo, &hi);
        if (lo >= hi) break;
        seq_phase(SH, lo, hi, S, br, tid, cta);
        gbar(cta, ++bt);
        zg_phase(SH, lvl, S, tid, cta);
        gbar(cta, ++bt);
    }
    /* ---- out: decoder + log_softmax ---- */
    if (cta < NN) {
        OutSh* o = (OutSh*)SH;
        int cnt  = g_count[cta];
        int slot = (cnt - 1) % HISTN;
        o->fin[tid] = g_hist[((size_t)cta*HISTN + slot)*HH + tid];
        __syncthreads();
        if (tid < PPV*OO) {
            int p = tid >> 6, qo = tid & 63;
            float acc = bd[p*OO + qo];
            #pragma unroll 4
            for (int h = 0; h < HH; ++h) acc += o->fin[h]*Wd[((size_t)p*HH + h)*OO + qo];
            o->lg[tid] = acc;
        }
        __syncthreads();
        if (tid < PPV*OO) {
            int p = tid >> 6, qo = tid & 63;
            float m = -1e30f;
            for (int k = 0; k < OO; ++k) m = fmaxf(m, o->lg[p*OO + k]);
            float sum = 0.f;
            for (int k = 0; k < OO; ++k) sum += expf(o->lg[p*OO + k] - m);
            out[((size_t)p*NN + cta)*OO + qo] = o->lg[tid] - m - logf(sum);
        }
    }
}

/* -------------------------------------------------------------------------- */
extern "C" void kernel_launch(void* const* d_in, const int* in_sizes, int n_in,
                              void* d_out, int out_size)
{
    const float* xa  = (const float*)d_in[0];
    const int*   nbr = (const int*)  d_in[1];
    const float* fm  = (const float*)d_in[2];
    const float* We  = (const float*)d_in[3];
    const float* be  = (const float*)d_in[4];
    const float* Wq  = (const float*)d_in[5];
    const float* bq  = (const float*)d_in[6];
    const float* Wk  = (const float*)d_in[7];
    /* d_in[8] = bk cancels in softmax */
    const float* Wr  = (const float*)d_in[9];
    const float* br  = (const float*)d_in[10];
    const float* Wm  = (const float*)d_in[11];
    const float* bm  = (const float*)d_in[12];
    const float* Wd  = (const float*)d_in[13];
    const float* bd  = (const float*)d_in[14];
    const int*   nS  = (const int*)  d_in[15];

    k_mega<<<NCTA, TPB2>>>(xa, nbr, fm, We, be, Wq, bq, Wk, Wr, br,
                           Wm, bm, Wd, bd, nS, (float*)d_out);
}

// round 14
// speedup vs baseline: 1.5496x; 1.2889x over previous
#include <cuda_runtime.h>
#include <cuda_fp16.h>
#include <mma.h>
#include <math.h>

using namespace nvcuda;

#define NN    512
#define FF    128
#define HH    256
#define MM    256
#define DEGN  8
#define HISTN 10
#define OO    64
#define PPV   2
#define MAXS  (10*NN)     /* 5120 */
#define NLVL  6
#define PCAP  640
#define BM    64
#define BN    64
#define BK    16
#define NCTA  512
#define TPB2  256
#define SHSZ  26688
#define NGRP  16          /* barrier groups (32 CTAs each) */

/* -------- persistent scratch (device globals) ----------------------------- */
__device__ float g_hist [NN*HISTN*HH];
__device__ __align__(16) __half g_XF  [NN*512];
__device__ __align__(16) __half g_CH  [PCAP*512];
__device__ __align__(16) __half g_ns_h[PCAP*HH];
__device__ __align__(16) __half g_BB  [512*512];   /* rows 0..255 = D, 256..511 = E=[A|Wm2] */
__device__ __align__(16) __half g_wm1h[HH*HH];
__device__ __align__(16) __half g_wr_h[HH*HH];
__device__ __align__(16) __half g_fm_h[NN*MM];
__device__ float g_bias [512];
__device__ int   g_bucket[MAXS];
__device__ int   g_boff  [NN+1];
__device__ int   g_count [NN];
__device__ __align__(128) unsigned g_grpc[NGRP][32];
__device__ unsigned g_rootc;
__device__ unsigned g_gen;

/* -------- shared overlays -------------------------------------------------- */
struct GrSh  { int sn[MAXS]; int T[NN]; int P[NN]; int cur[NN]; int chunk[16]; };
struct ZgSh  { __half sA[2][BM][BK]; __half sB[2][BK][BN]; float sO[BM][BN];
               const __half* P1[BM]; const __half* P2[BM]; };
struct SeqSh { float hist[HISTN][HH]; float kq[HH]; float vals[HH];
               float spart[8*HH]; float logit[16]; float attn[16]; int i0, i1; };
struct GaSh  { float sA[16][65]; float sB[16][65]; };
struct EncSh { float sx[FF]; };
struct OutSh { float fin[HH]; float lg[PPV*OO]; };

/* ------------------------- sync helpers ---------------------------------- */
__device__ __forceinline__ unsigned ldg_acq(const unsigned* p) {
    unsigned v;
    asm volatile("ld.acquire.gpu.global.b32 %0, [%1];" : "=r"(v) : "l"(p) : "memory");
    return v;
}
__device__ __forceinline__ void stg_rel(unsigned* p, unsigned v) {
    asm volatile("st.release.gpu.global.b32 [%0], %1;" :: "l"(p), "r"(v) : "memory");
}
__device__ __forceinline__ void gbar(int cta, unsigned target) {
    __syncthreads();
    if (threadIdx.x == 0) {
        __threadfence();
        int grp = cta >> 5;
        if (atomicAdd(&g_grpc[grp][0], 1u) == 31u) {
            *(volatile unsigned*)&g_grpc[grp][0] = 0u;
            __threadfence();
            if (atomicAdd(&g_rootc, 1u) == (unsigned)(NGRP-1)) {
                *(volatile unsigned*)&g_rootc = 0u;
                stg_rel(&g_gen, target);
            }
        }
        while ((int)(ldg_acq(&g_gen) - target) < 0) {}
    }
    __syncthreads();
}

__device__ __forceinline__ void level_bounds(int S, int level, int* plo, int* phi)
{
    int lo = 0, hi = (S < MAXS) ? S : MAXS;
    for (int l = 0; l < level; ++l) {
        lo = hi;
        int h2 = S + 8*hi;
        hi = (h2 > MAXS) ? MAXS : h2;
    }
    *plo = lo; *phi = hi;
}

/* ------------------- graph build (single CTA, 256 thr) -------------------- */
__device__ void graph_phase(char* SH, const int* __restrict__ nbr, int S, int tid)
{
    GrSh* g = (GrSh*)SH;
    for (int e = tid; e < S && e < MAXS; e += TPB2) g->sn[e] = e;
    __syncthreads();
    int known = (S < MAXS) ? S : MAXS;
    while (known < MAXS) {
        long long nx = (long long)S + 8LL*(long long)known;
        int next = (nx > MAXS) ? MAXS : (int)nx;
        for (int e = known + tid; e < next; e += TPB2) {
            int src = (e - S) >> 3;
            g->sn[e] = nbr[g->sn[src]*DEGN + ((e - S) & 7)];
        }
        __syncthreads();
        known = next;
    }
    for (int n = tid; n < NN; n += TPB2) { g->T[n] = 0; g->cur[n] = 0; }
    __syncthreads();
    for (int e = tid; e < MAXS; e += TPB2) atomicAdd(&g->T[g->sn[e]], 1);
    __syncthreads();
    {
        const int lane = tid & 31;
        #pragma unroll
        for (int pass = 0; pass < 2; ++pass) {
            int idx = pass*TPB2 + tid;
            int v = g->T[idx];
            #pragma unroll
            for (int o = 1; o < 32; o <<= 1) {
                int u = __shfl_up_sync(0xffffffffu, v, o);
                if (lane >= o) v += u;
            }
            g->P[idx] = v;
            if (lane == 31) g->chunk[idx >> 5] = v;
        }
        __syncthreads();
        if (tid == 0) {
            int run = 0;
            for (int c2 = 0; c2 < 16; ++c2) { int t6 = g->chunk[c2]; g->chunk[c2] = run; run += t6; }
        }
        __syncthreads();
        #pragma unroll
        for (int pass = 0; pass < 2; ++pass) {
            int idx = pass*TPB2 + tid;
            g->P[idx] += g->chunk[idx >> 5];
        }
        __syncthreads();
    }
    for (int n = tid; n < NN; n += TPB2) g_boff[n] = g->P[n] - g->T[n];
    if (tid == 0) g_boff[NN] = g->P[NN-1];
    __syncthreads();
    for (int e = tid; e < MAXS; e += TPB2) {
        int nd = g->sn[e];
        int pos = atomicAdd(&g->cur[nd], 1);
        g_bucket[(g->P[nd] - g->T[nd]) + pos] = e;
    }
    __syncthreads();
    for (int e = tid; e < MAXS; e += TPB2) g->sn[e] = g_bucket[e];
    __syncthreads();
    for (int n = tid; n < NN; n += TPB2) {
        int b0 = g->P[n] - g->T[n], b1 = g->P[n];
        for (int i = b0 + 1; i < b1; ++i) {
            int v = g->sn[i], j = i - 1;
            while (j >= b0 && g->sn[j] > v) { g->sn[j+1] = g->sn[j]; --j; }
            g->sn[j+1] = v;
        }
    }
    __syncthreads();
    for (int e = tid; e < MAXS; e += TPB2) g_bucket[e] = g->sn[e];
}

/* ------------------- gemmA tile: A=Wq@Wk^T / Wm2-pack / bias -------------- */
__device__ void gemmA_tile(char* SH, int t5,
                           const float* __restrict__ Wq, const float* __restrict__ Wk,
                           const float* __restrict__ Wm, const float* __restrict__ bq,
                           const float* __restrict__ bm, int t)
{
    const int bx = t5 >> 2, by = t5 & 3;
    __syncthreads();
    if (bx >= 4) {
        int k0 = (bx-4)*64, j0 = by*64;
        for (int i = t; i < 64*64; i += TPB2) {
            int k = k0 + (i >> 6), j = j0 + (i & 63);
            g_BB[(size_t)(256 + k)*512 + 256 + j] = __float2half(Wm[(size_t)(256 + k)*MM + j]);
        }
        if (bx == 4 && by == 0) {
            int w = t >> 5, l = t & 31;
            for (int r0 = 0; r0 < HH; r0 += 8) {
                int r = r0 + w;
                float p = 0.f;
                #pragma unroll
                for (int k = 0; k < 8; ++k) { int h = l + k*32; p += Wk[(size_t)r*HH + h]*bq[h]; }
                #pragma unroll
                for (int o = 16; o > 0; o >>= 1) p += __shfl_down_sync(0xffffffffu, p, o);
                if (l == 0) g_bias[r] = p;
            }
            g_bias[256 + t] = bm[t];
        }
        return;
    }
    GaSh* ga = (GaSh*)SH;
    const int i0 = bx*64, j0 = by*64;
    const int tx = t & 15, ty = t >> 4;
    float acc[4][4];
    #pragma unroll
    for (int a = 0; a < 4; ++a)
        #pragma unroll
        for (int b = 0; b < 4; ++b) acc[a][b] = 0.f;
    for (int kt = 0; kt < HH; kt += 16) {
        int lr = t >> 2, lh = (t & 3)*4;
        float4 va = *(const float4*)(Wq + (size_t)(i0+lr)*HH + kt + lh);
        ga->sA[lh+0][lr]=va.x; ga->sA[lh+1][lr]=va.y; ga->sA[lh+2][lr]=va.z; ga->sA[lh+3][lr]=va.w;
        float4 vb = *(const float4*)(Wk + (size_t)(j0+lr)*HH + kt + lh);
        ga->sB[lh+0][lr]=vb.x; ga->sB[lh+1][lr]=vb.y; ga->sB[lh+2][lr]=vb.z; ga->sB[lh+3][lr]=vb.w;
        __syncthreads();
        #pragma unroll
        for (int h = 0; h < 16; ++h) {
            float ra[4], rb[4];
            #pragma unroll
            for (int a = 0; a < 4; ++a) ra[a] = ga->sA[h][ty*4 + a];
            #pragma unroll
            for (int b = 0; b < 4; ++b) rb[b] = ga->sB[h][tx*4 + b];
            #pragma unroll
            for (int a = 0; a < 4; ++a)
                #pragma unroll
                for (int b = 0; b < 4; ++b) acc[a][b] += ra[a]*rb[b];
        }
        __syncthreads();
    }
    #pragma unroll
    for (int a = 0; a < 4; ++a)
        #pragma unroll
        for (int b = 0; b < 4; ++b)
            g_BB[(size_t)(256 + i0 + ty*4 + a)*512 + (j0 + tx*4 + b)] = __float2half(acc[a][b]);
}

/* ------------------- gemmD tile: D = Wm1 @ E (2-deep prefetch) ------------ */
__device__ void gemmD_tile(char* SH, int t5, int tid)
{
    ZgSh* z = (ZgSh*)SH;
    const int m0 = (t5 >> 3) * BM, n0 = (t5 & 7) * BN;
    const int wid = tid >> 5, wr = wid & 3, wc = wid >> 2;
    const int ar = tid >> 2, ac = (tid & 3)*4;
    const int brw = tid >> 4, bc = (tid & 15)*4;
    const int KT = HH / BK;
    __syncthreads();
    wmma::fragment<wmma::accumulator,16,16,16,float> acc[2];
    wmma::fill_fragment(acc[0], 0.f);
    wmma::fill_fragment(acc[1], 0.f);
    #define LDA_D(k) (*(const uint2*)(g_wm1h + (size_t)(m0+ar)*HH + (k)*BK + ac))
    #define LDB_D(k) (*(const uint2*)(g_BB + (size_t)(256 + (k)*BK + brw)*512 + n0 + bc))
    uint2 rA[2], rB[2];
    {
        uint2 tA = LDA_D(0), tB = LDB_D(0);
        *(uint2*)&z->sA[0][ar][ac] = tA;
        *(uint2*)&z->sB[0][brw][bc] = tB;
        rA[1] = LDA_D(1); rB[1] = LDB_D(1);
        rA[0] = LDA_D(2); rB[0] = LDB_D(2);
    }
    __syncthreads();
    for (int k = 0; k < KT; ++k) {
        const int p = k & 1, q = p ^ 1;
        if (k + 1 < KT) {
            *(uint2*)&z->sA[q][ar][ac] = rA[q];
            *(uint2*)&z->sB[q][brw][bc] = rB[q];
        }
        if (k + 3 < KT) { rA[q] = LDA_D(k+3); rB[q] = LDB_D(k+3); }
        wmma::fragment<wmma::matrix_a,16,16,16,__half,wmma::row_major> fa;
        wmma::load_matrix_sync(fa, &z->sA[p][wr*16][0], BK);
        #pragma unroll
        for (int j = 0; j < 2; ++j) {
            wmma::fragment<wmma::matrix_b,16,16,16,__half,wmma::row_major> fb;
            wmma::load_matrix_sync(fb, &z->sB[p][0][wc*32 + j*16], BN);
            wmma::mma_sync(acc[j], fa, fb, acc[j]);
        }
        __syncthreads();
    }
    #undef LDA_D
    #undef LDB_D
    wmma::store_matrix_sync(&z->sO[wr*16][wc*32],      acc[0], BN, wmma::mem_row_major);
    wmma::store_matrix_sync(&z->sO[wr*16][wc*32 + 16], acc[1], BN, wmma::mem_row_major);
    __syncthreads();
    for (int idx = tid; idx < BM*BN; idx += TPB2) {
        int r = idx >> 6, nl = idx & 63;
        g_BB[(size_t)(m0 + r)*512 + n0 + nl] = __float2half(z->sO[r][nl]);
    }
}

/* ------------------- zg tile: CH/XF = [NS|W2] @ BB + bias (2-deep) -------- */
__device__ void zg_tile(char* SH, int level, int S, int rlo, int rhi,
                        int m0, int n0, int tid)
{
    ZgSh* z = (ZgSh*)SH;
    __syncthreads();
    if (tid < BM) {
        int p = rlo + m0 + tid;
        if (p < rhi) {
            if (level < 0) {
                z->P1[tid] = 0;
                z->P2[tid] = g_fm_h + (size_t)p*MM;
            } else {
                z->P1[tid] = g_ns_h + (size_t)p*HH;
                z->P2[tid] = (p < S) ? (g_XF + (size_t)p*512 + 256)
                                     : (g_CH + (size_t)((p - S) >> 3)*512 + 256);
            }
        } else { z->P1[tid] = 0; z->P2[tid] = 0; }
    }
    __syncthreads();
    const int wid = tid >> 5, wr = wid & 3, wc = wid >> 2;
    const int ar = tid >> 2, ac = (tid & 3)*4;
    const int brw = tid >> 4, bc = (tid & 15)*4;
    const __half* p1 = z->P1[ar];
    const __half* p2 = z->P2[ar];
    wmma::fragment<wmma::accumulator,16,16,16,float> acc[2];
    wmma::fill_fragment(acc[0], 0.f);
    wmma::fill_fragment(acc[1], 0.f);
    const int KT = 512 / BK;
    #define LDA_Z(k) ({ int kt = (k)*BK; const __half* b_ = (kt < 256) ? p1 : p2; \
                        b_ ? *(const uint2*)(b_ + (kt & 255) + ac) : make_uint2(0u,0u); })
    #define LDB_Z(k) (*(const uint2*)(g_BB + (size_t)((k)*BK + brw)*512 + n0 + bc))
    uint2 rA[2], rB[2];
    {
        uint2 tA = LDA_Z(0), tB = LDB_Z(0);
        *(uint2*)&z->sA[0][ar][ac] = tA;
        *(uint2*)&z->sB[0][brw][bc] = tB;
        rA[1] = LDA_Z(1); rB[1] = LDB_Z(1);
        rA[0] = LDA_Z(2); rB[0] = LDB_Z(2);
    }
    __syncthreads();
    for (int k = 0; k < KT; ++k) {
        const int p = k & 1, q = p ^ 1;
        if (k + 1 < KT) {
            *(uint2*)&z->sA[q][ar][ac] = rA[q];
            *(uint2*)&z->sB[q][brw][bc] = rB[q];
        }
        if (k + 3 < KT) { rA[q] = LDA_Z(k+3); rB[q] = LDB_Z(k+3); }
        wmma::fragment<wmma::matrix_a,16,16,16,__half,wmma::row_major> fa;
        wmma::load_matrix_sync(fa, &z->sA[p][wr*16][0], BK);
        #pragma unroll
        for (int j = 0; j < 2; ++j) {
            wmma::fragment<wmma::matrix_b,16,16,16,__half,wmma::row_major> fb;
            wmma::load_matrix_sync(fb, &z->sB[p][0][wc*32 + j*16], BN);
            wmma::mma_sync(acc[j], fa, fb, acc[j]);
        }
        __syncthreads();
    }
    #undef LDA_Z
    #undef LDB_Z
    wmma::store_matrix_sync(&z->sO[wr*16][wc*32],      acc[0], BN, wmma::mem_row_major);
    wmma::store_matrix_sync(&z->sO[wr*16][wc*32 + 16], acc[1], BN, wmma::mem_row_major);
    __syncthreads();
    __half* outp = (level < 0) ? g_XF : g_CH;
    for (int idx = tid; idx < BM*BN; idx += TPB2) {
        int r = idx >> 6, nl = idx & 63;
        int pp = rlo + m0 + r;
        if (pp < rhi) {
            int n = n0 + nl;
            outp[(size_t)pp*512 + n] = __float2half(z->sO[r][nl] + g_bias[n]);
        }
    }
}

__device__ void zg_phase(char* SH, int level, int S, int tid, int cta)
{
    int rlo, rhi;
    if (level < 0) { rlo = 0; rhi = (S < NN) ? S : NN; }
    else {
        int lo, hi; level_bounds(S, level, &lo, &hi);
        int PM = (MAXS - S + 7) >> 3;
        rlo = lo; rhi = (hi < PM) ? hi : PM;
    }
    if (rlo >= rhi) return;
    int rows = rhi - rlo, RT = (rows + BM - 1) / BM;
    for (int t5 = cta; t5 < RT*8; t5 += NCTA)
        zg_tile(SH, level, S, rlo, rhi, (t5 >> 3)*BM, (t5 & 7)*BN, tid);
}

/* ------- seq: per-node chain within level (optimized per-visit path) ------ */
__device__ void seq_phase(char* SH, int lo, int hi, int S,
                          const float* __restrict__ br, int tid, int cta)
{
    if (cta >= NN) return;
    SeqSh* q = (SeqSh*)SH;
    const int nd = cta;
    const int PM = (MAXS - S + 7) >> 3;
    if (tid == 0) {
        int b0 = g_boff[nd], b1 = g_boff[nd+1];
        int i0 = b0; while (i0 < b1 && g_bucket[i0] < lo) ++i0;
        int i1 = i0; while (i1 < b1 && g_bucket[i1] < hi) ++i1;
        q->i0 = i0; q->i1 = i1;
    }
    __syncthreads();
    const int i0 = q->i0, i1 = q->i1;
    if (i0 >= i1) return;
    int cnt = g_count[nd];
    const int wid = tid >> 5, lid = tid & 31;
    const float brv = br[tid];

    /* load node hist ring into smem once per level */
    #pragma unroll
    for (int r = 0; r < HISTN; ++r)
        q->hist[r][tid] = g_hist[((size_t)nd*HISTN + r)*HH + tid];
    __syncthreads();

    for (int i = i0; i < i1; ++i) {
        const int sstep = g_bucket[i];
        {
            const __half* kqp = (sstep < S)
                ? (g_XF + (size_t)sstep*512)
                : (g_CH + (size_t)((sstep - S) >> 3)*512);
            q->kq[tid] = __half2float(__ldg(kqp + tid));
        }
        __syncthreads();                               /* (1) kq ready */
        const int nv   = (cnt < HISTN) ? cnt : HISTN;
        const int slot = cnt % HISTN;
        /* logits: warp per slot, 2 passes */
        #pragma unroll
        for (int pass = 0; pass < 2; ++pass) {
            int sl = wid + pass*8;
            if (sl < nv) {
                const float* hp = q->hist[sl];
                float p = 0.f;
                #pragma unroll
                for (int k = 0; k < 8; ++k) { int h = lid + k*32; p += hp[h]*q->kq[h]; }
                #pragma unroll
                for (int o = 16; o > 0; o >>= 1) p += __shfl_down_sync(0xffffffffu, p, o);
                if (lid == 0) q->logit[sl] = p * 0.0625f;
            }
        }
        __syncthreads();                               /* (2) logits ready */
        /* softmax on warp 0 via shuffles */
        if (tid < 32) {
            float lg = (tid < nv) ? q->logit[tid] : -1e30f;
            float m = lg;
            #pragma unroll
            for (int o = 16; o > 0; o >>= 1) m = fmaxf(m, __shfl_xor_sync(0xffffffffu, m, o));
            float e = (tid < nv) ? __expf(lg - m) : 0.f;
            float s = e;
            #pragma unroll
            for (int o = 16; o > 0; o >>= 1) s += __shfl_xor_sync(0xffffffffu, s, o);
            if (tid < 16) q->attn[tid] = e / s;
        }
        __syncthreads();                               /* (3) attn ready */
        {
            float v = 0.f;
            #pragma unroll 2
            for (int k = 0; k < nv; ++k) v += q->attn[k]*q->hist[k][tid];
            q->vals[tid] = v;
        }
        __syncthreads();                               /* (4) vals ready */
        /* ns = vals @ Wr + br : warp w owns rows 32w..32w+31, lane owns 8 cols */
        {
            float a0=0,a1=0,a2=0,a3=0,a4=0,a5=0,a6=0,a7=0;
            const int r0 = wid*32;
            const float4* Wv = (const float4*)g_wr_h;   /* 32 float4 per 256-half row */
            #pragma unroll 8
            for (int r = r0; r < r0+32; ++r) {
                float x = q->vals[r];
                float4 w = __ldg(&Wv[(size_t)r*32 + lid]);
                const half2* hp = (const half2*)&w;
                float2 f0 = __half22float2(hp[0]);
                float2 f1 = __half22float2(hp[1]);
                float2 f2 = __half22float2(hp[2]);
                float2 f3 = __half22float2(hp[3]);
                a0 += x*f0.x; a1 += x*f0.y; a2 += x*f1.x; a3 += x*f1.y;
                a4 += x*f2.x; a5 += x*f2.y; a6 += x*f3.x; a7 += x*f3.y;
            }
            float4* sp4 = (float4*)q->spart;
            sp4[(size_t)wid*64 + lid*2 + 0] = make_float4(a0,a1,a2,a3);
            sp4[(size_t)wid*64 + lid*2 + 1] = make_float4(a4,a5,a6,a7);
        }
        __syncthreads();                               /* (5) partials ready */
        {
            float r = brv;
            #pragma unroll
            for (int k = 0; k < 8; ++k) r += q->spart[k*HH + tid];
            q->hist[slot][tid] = r;
            g_hist[((size_t)nd*HISTN + slot)*HH + tid] = r;
            if (sstep < PM) g_ns_h[(size_t)sstep*HH + tid] = __float2half(r);
        }
        ++cnt;
        __syncthreads();                               /* (6) hist updated */
    }
    if (tid == 0) g_count[nd] = cnt;
}

/* ------------------- mega kernel ------------------------------------------ */
__global__ void __launch_bounds__(TPB2, 4)
k_mega(const float* __restrict__ xa, const int* __restrict__ nbr,
       const float* __restrict__ fm,
       const float* __restrict__ We, const float* __restrict__ be,
       const float* __restrict__ Wq, const float* __restrict__ bq,
       const float* __restrict__ Wk,
       const float* __restrict__ Wr, const float* __restrict__ br,
       const float* __restrict__ Wm, const float* __restrict__ bm,
       const float* __restrict__ Wd, const float* __restrict__ bd,
       const int* __restrict__ nS, float* __restrict__ out)
{
    __shared__ __align__(16) char SH[SHSZ];
    __shared__ unsigned sh_base;
    const int cta = blockIdx.x, tid = threadIdx.x;
    const int S = *nS;

    if (tid == 0) sh_base = *(volatile unsigned*)&g_gen;
    __syncthreads();
    unsigned bt = sh_base;

    /* ---- P0: graph (CTA 511) || encode + packs + gemmA (others) ---- */
    if (cta == NCTA-1) {
        graph_phase(SH, nbr, S, tid);
    } else {
        EncSh* es = (EncSh*)SH;
        for (int n = cta; n < NN; n += NCTA-1) {
            if (tid < FF) es->sx[tid] = xa[n*FF + tid];
            __syncthreads();
            float acc = be[tid];
            #pragma unroll 4
            for (int f = 0; f < FF; ++f) acc += es->sx[f] * We[f*HH + tid];
            g_hist[((size_t)n*HISTN + 0)*HH + tid] = acc;
            g_fm_h[(size_t)n*MM + tid] = __float2half(fm[(size_t)n*MM + tid]);
            if (tid == 0) g_count[n] = 1;
            __syncthreads();
        }
        for (int r = cta; r < HH; r += NCTA-1) {
            g_wm1h[(size_t)r*MM + tid] = __float2half(Wm[(size_t)r*MM + tid]);
            float s = Wr[r*HH + tid] + Wr[(HH + r)*HH + tid]
                    + Wr[(2*HH + r)*HH + tid] + Wr[(3*HH + r)*HH + tid];
            g_wr_h[r*HH + tid] = __float2half(s);
        }
        for (int t5 = cta; t5 < 32; t5 += NCTA-1)
            gemmA_tile(SH, t5, Wq, Wk, Wm, bq, bm, tid);
    }
    gbar(cta, ++bt);
    for (int t5 = cta; t5 < 32; t5 += NCTA) gemmD_tile(SH, t5, tid);
    gbar(cta, ++bt);
    zg_phase(SH, -1, S, tid, cta);
    gbar(cta, ++bt);
    for (int lvl = 0; lvl < NLVL; ++lvl) {
        int lo, hi; level_bounds(S, lvl, &lo, &hi);
        if (lo >= hi) break;
        seq_phase(SH, lo, hi, S, br, tid, cta);
        gbar(cta, ++bt);
        zg_phase(SH, lvl, S, tid, cta);
        gbar(cta, ++bt);
    }
    /* ---- out: decoder + log_softmax ---- */
    if (cta < NN) {
        OutSh* o = (OutSh*)SH;
        int cnt  = g_count[cta];
        int slot = (cnt - 1) % HISTN;
        o->fin[tid] = g_hist[((size_t)cta*HISTN + slot)*HH + tid];
        __syncthreads();
        if (tid < PPV*OO) {
            int p = tid >> 6, qo = tid & 63;
            float acc = bd[p*OO + qo];
            #pragma unroll 4
            for (int h = 0; h < HH; ++h) acc += o->fin[h]*Wd[((size_t)p*HH + h)*OO + qo];
            o->lg[tid] = acc;
        }
        __syncthreads();
        if (tid < PPV*OO) {
            int p = tid >> 6, qo = tid & 63;
            float m = -1e30f;
            for (int k = 0; k < OO; ++k) m = fmaxf(m, o->lg[p*OO + k]);
            float sum = 0.f;
            for (int k = 0; k < OO; ++k) sum += expf(o->lg[p*OO + k] - m);
            out[((size_t)p*NN + cta)*OO + qo] = o->lg[tid] - m - logf(sum);
        }
    }
}

/* -------------------------------------------------------------------------- */
extern "C" void kernel_launch(void* const* d_in, const int* in_sizes, int n_in,
                              void* d_out, int out_size)
{
    const float* xa  = (const float*)d_in[0];
    const int*   nbr = (const int*)  d_in[1];
    const float* fm  = (const float*)d_in[2];
    const float* We  = (const float*)d_in[3];
    const float* be  = (const float*)d_in[4];
    const float* Wq  = (const float*)d_in[5];
    const float* bq  = (const float*)d_in[6];
    const float* Wk  = (const float*)d_in[7];
    /* d_in[8] = bk cancels in softmax */
    const float* Wr  = (const float*)d_in[9];
    const float* br  = (const float*)d_in[10];
    const float* Wm  = (const float*)d_in[11];
    const float* bm  = (const float*)d_in[12];
    const float* Wd  = (const float*)d_in[13];
    const float* bd  = (const float*)d_in[14];
    const int*   nS  = (const int*)  d_in[15];

    k_mega<<<NCTA, TPB2>>>(xa, nbr, fm, We, be, Wq, bq, Wk, Wr, br,
                           Wm, bm, Wd, bd, nS, (float*)d_out);
}

// round 15
// speedup vs baseline: 1.5641x; 1.0093x over previous
#include <cuda_runtime.h>
#include <cuda_fp16.h>
#include <mma.h>
#include <math.h>

using namespace nvcuda;

#define NN    512
#define FF    128
#define HH    256
#define MM    256
#define DEGN  8
#define HISTN 10
#define OO    64
#define PPV   2
#define MAXS  (10*NN)     /* 5120 */
#define NLVL  6
#define PCAP  640
#define BM    64
#define BN    64
#define BK    16
#define NCTA  512
#define TPB2  256
#define SHSZ  26688
#define NGRP  16

/* -------- persistent scratch (device globals) ----------------------------- */
__device__ float g_hist [NN*HISTN*HH];
__device__ __align__(16) __half g_XF  [NN*512];
__device__ __align__(16) __half g_CH  [PCAP*512];
__device__ __align__(16) __half g_ns_h[PCAP*HH];
__device__ __align__(16) __half g_BB  [512*512];   /* rows 0..255 = D, 256..511 = E=[A|Wm2] */
__device__ __align__(16) __half g_wm1h[HH*HH];
__device__ __align__(16) __half g_wr_h[HH*HH];
__device__ __align__(16) __half g_fm_h[NN*MM];
__device__ float g_bias [512];
__device__ int   g_bucket[MAXS];
__device__ int   g_boff  [NN+1];
__device__ int   g_count [NN];
__device__ __align__(128) unsigned g_grpc[NGRP][32];
__device__ unsigned g_rootc;
__device__ unsigned g_gen;

/* -------- shared overlays -------------------------------------------------- */
struct GrSh  { int sn[MAXS]; int T[NN]; int P[NN]; int cur[NN]; int chunk[16]; };
struct ZgSh  { __half sA[2][BM][BK]; __half sB[2][BK][BN]; float sO[BM][BN];
               const __half* P1[BM]; const __half* P2[BM]; };
struct SeqSh { float hist[HISTN][HH]; float kq[2][HH]; float vals[HH];
               float spart[8*HH]; float logit[16]; int i0, i1; };
struct GaSh  { float sA[16][65]; float sB[16][65]; };
struct EncSh { float sx[FF]; };
struct OutSh { float fin[HH]; float lg[PPV*OO]; };

/* ------------------------- sync helpers ---------------------------------- */
__device__ __forceinline__ unsigned ldg_acq(const unsigned* p) {
    unsigned v;
    asm volatile("ld.acquire.gpu.global.b32 %0, [%1];" : "=r"(v) : "l"(p) : "memory");
    return v;
}
__device__ __forceinline__ void stg_rel(unsigned* p, unsigned v) {
    asm volatile("st.release.gpu.global.b32 [%0], %1;" :: "l"(p), "r"(v) : "memory");
}
__device__ __forceinline__ void gbar(int cta, unsigned target) {
    __syncthreads();
    if (threadIdx.x == 0) {
        __threadfence();
        int grp = cta >> 5;
        if (atomicAdd(&g_grpc[grp][0], 1u) == 31u) {
            *(volatile unsigned*)&g_grpc[grp][0] = 0u;
            __threadfence();
            if (atomicAdd(&g_rootc, 1u) == (unsigned)(NGRP-1)) {
                *(volatile unsigned*)&g_rootc = 0u;
                stg_rel(&g_gen, target);
            }
        }
        while ((int)(ldg_acq(&g_gen) - target) < 0) {}
    }
    __syncthreads();
}

__device__ __forceinline__ void level_bounds(int S, int level, int* plo, int* phi)
{
    int lo = 0, hi = (S < MAXS) ? S : MAXS;
    for (int l = 0; l < level; ++l) {
        lo = hi;
        int h2 = S + 8*hi;
        hi = (h2 > MAXS) ? MAXS : h2;
    }
    *plo = lo; *phi = hi;
}

/* ------------------- graph build (single CTA, 256 thr) -------------------- */
__device__ void graph_phase(char* SH, const int* __restrict__ nbr, int S, int tid)
{
    GrSh* g = (GrSh*)SH;
    for (int e = tid; e < S && e < MAXS; e += TPB2) g->sn[e] = e;
    __syncthreads();
    int known = (S < MAXS) ? S : MAXS;
    while (known < MAXS) {
        long long nx = (long long)S + 8LL*(long long)known;
        int next = (nx > MAXS) ? MAXS : (int)nx;
        for (int e = known + tid; e < next; e += TPB2) {
            int src = (e - S) >> 3;
            g->sn[e] = nbr[g->sn[src]*DEGN + ((e - S) & 7)];
        }
        __syncthreads();
        known = next;
    }
    for (int n = tid; n < NN; n += TPB2) { g->T[n] = 0; g->cur[n] = 0; }
    __syncthreads();
    for (int e = tid; e < MAXS; e += TPB2) atomicAdd(&g->T[g->sn[e]], 1);
    __syncthreads();
    {
        const int lane = tid & 31;
        #pragma unroll
        for (int pass = 0; pass < 2; ++pass) {
            int idx = pass*TPB2 + tid;
            int v = g->T[idx];
            #pragma unroll
            for (int o = 1; o < 32; o <<= 1) {
                int u = __shfl_up_sync(0xffffffffu, v, o);
                if (lane >= o) v += u;
            }
            g->P[idx] = v;
            if (lane == 31) g->chunk[idx >> 5] = v;
        }
        __syncthreads();
        if (tid == 0) {
            int run = 0;
            for (int c2 = 0; c2 < 16; ++c2) { int t6 = g->chunk[c2]; g->chunk[c2] = run; run += t6; }
        }
        __syncthreads();
        #pragma unroll
        for (int pass = 0; pass < 2; ++pass) {
            int idx = pass*TPB2 + tid;
            g->P[idx] += g->chunk[idx >> 5];
        }
        __syncthreads();
    }
    for (int n = tid; n < NN; n += TPB2) g_boff[n] = g->P[n] - g->T[n];
    if (tid == 0) g_boff[NN] = g->P[NN-1];
    __syncthreads();
    for (int e = tid; e < MAXS; e += TPB2) {
        int nd = g->sn[e];
        int pos = atomicAdd(&g->cur[nd], 1);
        g_bucket[(g->P[nd] - g->T[nd]) + pos] = e;
    }
    __syncthreads();
    for (int e = tid; e < MAXS; e += TPB2) g->sn[e] = g_bucket[e];
    __syncthreads();
    for (int n = tid; n < NN; n += TPB2) {
        int b0 = g->P[n] - g->T[n], b1 = g->P[n];
        for (int i = b0 + 1; i < b1; ++i) {
            int v = g->sn[i], j = i - 1;
            while (j >= b0 && g->sn[j] > v) { g->sn[j+1] = g->sn[j]; --j; }
            g->sn[j+1] = v;
        }
    }
    __syncthreads();
    for (int e = tid; e < MAXS; e += TPB2) g_bucket[e] = g->sn[e];
}

/* ------------------- gemmA tile: A=Wq@Wk^T / Wm2-pack / bias -------------- */
__device__ void gemmA_tile(char* SH, int t5,
                           const float* __restrict__ Wq, const float* __restrict__ Wk,
                           const float* __restrict__ Wm, const float* __restrict__ bq,
                           const float* __restrict__ bm, int t)
{
    const int bx = t5 >> 2, by = t5 & 3;
    __syncthreads();
    if (bx >= 4) {
        int k0 = (bx-4)*64, j0 = by*64;
        for (int i = t; i < 64*64; i += TPB2) {
            int k = k0 + (i >> 6), j = j0 + (i & 63);
            g_BB[(size_t)(256 + k)*512 + 256 + j] = __float2half(Wm[(size_t)(256 + k)*MM + j]);
        }
        if (bx == 4 && by == 0) {
            int w = t >> 5, l = t & 31;
            for (int r0 = 0; r0 < HH; r0 += 8) {
                int r = r0 + w;
                float p = 0.f;
                #pragma unroll
                for (int k = 0; k < 8; ++k) { int h = l + k*32; p += Wk[(size_t)r*HH + h]*bq[h]; }
                #pragma unroll
                for (int o = 16; o > 0; o >>= 1) p += __shfl_down_sync(0xffffffffu, p, o);
                if (l == 0) g_bias[r] = p;
            }
            g_bias[256 + t] = bm[t];
        }
        return;
    }
    GaSh* ga = (GaSh*)SH;
    const int i0 = bx*64, j0 = by*64;
    const int tx = t & 15, ty = t >> 4;
    float acc[4][4];
    #pragma unroll
    for (int a = 0; a < 4; ++a)
        #pragma unroll
        for (int b = 0; b < 4; ++b) acc[a][b] = 0.f;
    for (int kt = 0; kt < HH; kt += 16) {
        int lr = t >> 2, lh = (t & 3)*4;
        float4 va = *(const float4*)(Wq + (size_t)(i0+lr)*HH + kt + lh);
        ga->sA[lh+0][lr]=va.x; ga->sA[lh+1][lr]=va.y; ga->sA[lh+2][lr]=va.z; ga->sA[lh+3][lr]=va.w;
        float4 vb = *(const float4*)(Wk + (size_t)(j0+lr)*HH + kt + lh);
        ga->sB[lh+0][lr]=vb.x; ga->sB[lh+1][lr]=vb.y; ga->sB[lh+2][lr]=vb.z; ga->sB[lh+3][lr]=vb.w;
        __syncthreads();
        #pragma unroll
        for (int h = 0; h < 16; ++h) {
            float ra[4], rb[4];
            #pragma unroll
            for (int a = 0; a < 4; ++a) ra[a] = ga->sA[h][ty*4 + a];
            #pragma unroll
            for (int b = 0; b < 4; ++b) rb[b] = ga->sB[h][tx*4 + b];
            #pragma unroll
            for (int a = 0; a < 4; ++a)
                #pragma unroll
                for (int b = 0; b < 4; ++b) acc[a][b] += ra[a]*rb[b];
        }
        __syncthreads();
    }
    #pragma unroll
    for (int a = 0; a < 4; ++a)
        #pragma unroll
        for (int b = 0; b < 4; ++b)
            g_BB[(size_t)(256 + i0 + ty*4 + a)*512 + (j0 + tx*4 + b)] = __float2half(acc[a][b]);
}

/* ------------------- gemmD tile: D = Wm1 @ E (2-deep prefetch) ------------ */
__device__ void gemmD_tile(char* SH, int t5, int tid)
{
    ZgSh* z = (ZgSh*)SH;
    const int m0 = (t5 >> 3) * BM, n0 = (t5 & 7) * BN;
    const int wid = tid >> 5, wr = wid & 3, wc = wid >> 2;
    const int ar = tid >> 2, ac = (tid & 3)*4;
    const int brw = tid >> 4, bc = (tid & 15)*4;
    const int KT = HH / BK;
    __syncthreads();
    wmma::fragment<wmma::accumulator,16,16,16,float> acc[2];
    wmma::fill_fragment(acc[0], 0.f);
    wmma::fill_fragment(acc[1], 0.f);
    #define LDA_D(k) (*(const uint2*)(g_wm1h + (size_t)(m0+ar)*HH + (k)*BK + ac))
    #define LDB_D(k) (*(const uint2*)(g_BB + (size_t)(256 + (k)*BK + brw)*512 + n0 + bc))
    uint2 rA[2], rB[2];
    {
        uint2 tA = LDA_D(0), tB = LDB_D(0);
        *(uint2*)&z->sA[0][ar][ac] = tA;
        *(uint2*)&z->sB[0][brw][bc] = tB;
        rA[1] = LDA_D(1); rB[1] = LDB_D(1);
        rA[0] = LDA_D(2); rB[0] = LDB_D(2);
    }
    __syncthreads();
    for (int k = 0; k < KT; ++k) {
        const int p = k & 1, q = p ^ 1;
        if (k + 1 < KT) {
            *(uint2*)&z->sA[q][ar][ac] = rA[q];
            *(uint2*)&z->sB[q][brw][bc] = rB[q];
        }
        if (k + 3 < KT) { rA[q] = LDA_D(k+3); rB[q] = LDB_D(k+3); }
        wmma::fragment<wmma::matrix_a,16,16,16,__half,wmma::row_major> fa;
        wmma::load_matrix_sync(fa, &z->sA[p][wr*16][0], BK);
        #pragma unroll
        for (int j = 0; j < 2; ++j) {
            wmma::fragment<wmma::matrix_b,16,16,16,__half,wmma::row_major> fb;
            wmma::load_matrix_sync(fb, &z->sB[p][0][wc*32 + j*16], BN);
            wmma::mma_sync(acc[j], fa, fb, acc[j]);
        }
        __syncthreads();
    }
    #undef LDA_D
    #undef LDB_D
    wmma::store_matrix_sync(&z->sO[wr*16][wc*32],      acc[0], BN, wmma::mem_row_major);
    wmma::store_matrix_sync(&z->sO[wr*16][wc*32 + 16], acc[1], BN, wmma::mem_row_major);
    __syncthreads();
    for (int idx = tid; idx < BM*BN; idx += TPB2) {
        int r = idx >> 6, nl = idx & 63;
        g_BB[(size_t)(m0 + r)*512 + n0 + nl] = __float2half(z->sO[r][nl]);
    }
}

/* ------------------- zg tile: CH/XF = [NS|W2] @ BB + bias (2-deep) -------- */
__device__ void zg_tile(char* SH, int level, int S, int rlo, int rhi,
                        int m0, int n0, int tid)
{
    ZgSh* z = (ZgSh*)SH;
    __syncthreads();
    if (tid < BM) {
        int p = rlo + m0 + tid;
        if (p < rhi) {
            if (level < 0) {
                z->P1[tid] = 0;
                z->P2[tid] = g_fm_h + (size_t)p*MM;
            } else {
                z->P1[tid] = g_ns_h + (size_t)p*HH;
                z->P2[tid] = (p < S) ? (g_XF + (size_t)p*512 + 256)
                                     : (g_CH + (size_t)((p - S) >> 3)*512 + 256);
            }
        } else { z->P1[tid] = 0; z->P2[tid] = 0; }
    }
    __syncthreads();
    const int wid = tid >> 5, wr = wid & 3, wc = wid >> 2;
    const int ar = tid >> 2, ac = (tid & 3)*4;
    const int brw = tid >> 4, bc = (tid & 15)*4;
    const __half* p1 = z->P1[ar];
    const __half* p2 = z->P2[ar];
    wmma::fragment<wmma::accumulator,16,16,16,float> acc[2];
    wmma::fill_fragment(acc[0], 0.f);
    wmma::fill_fragment(acc[1], 0.f);
    const int KT = 512 / BK;
    #define LDA_Z(k) ({ int kt = (k)*BK; const __half* b_ = (kt < 256) ? p1 : p2; \
                        b_ ? *(const uint2*)(b_ + (kt & 255) + ac) : make_uint2(0u,0u); })
    #define LDB_Z(k) (*(const uint2*)(g_BB + (size_t)((k)*BK + brw)*512 + n0 + bc))
    uint2 rA[2], rB[2];
    {
        uint2 tA = LDA_Z(0), tB = LDB_Z(0);
        *(uint2*)&z->sA[0][ar][ac] = tA;
        *(uint2*)&z->sB[0][brw][bc] = tB;
        rA[1] = LDA_Z(1); rB[1] = LDB_Z(1);
        rA[0] = LDA_Z(2); rB[0] = LDB_Z(2);
    }
    __syncthreads();
    for (int k = 0; k < KT; ++k) {
        const int p = k & 1, q = p ^ 1;
        if (k + 1 < KT) {
            *(uint2*)&z->sA[q][ar][ac] = rA[q];
            *(uint2*)&z->sB[q][brw][bc] = rB[q];
        }
        if (k + 3 < KT) { rA[q] = LDA_Z(k+3); rB[q] = LDB_Z(k+3); }
        wmma::fragment<wmma::matrix_a,16,16,16,__half,wmma::row_major> fa;
        wmma::load_matrix_sync(fa, &z->sA[p][wr*16][0], BK);
        #pragma unroll
        for (int j = 0; j < 2; ++j) {
            wmma::fragment<wmma::matrix_b,16,16,16,__half,wmma::row_major> fb;
            wmma::load_matrix_sync(fb, &z->sB[p][0][wc*32 + j*16], BN);
            wmma::mma_sync(acc[j], fa, fb, acc[j]);
        }
        __syncthreads();
    }
    #undef LDA_Z
    #undef LDB_Z
    wmma::store_matrix_sync(&z->sO[wr*16][wc*32],      acc[0], BN, wmma::mem_row_major);
    wmma::store_matrix_sync(&z->sO[wr*16][wc*32 + 16], acc[1], BN, wmma::mem_row_major);
    __syncthreads();
    __half* outp = (level < 0) ? g_XF : g_CH;
    for (int idx = tid; idx < BM*BN; idx += TPB2) {
        int r = idx >> 6, nl = idx & 63;
        int pp = rlo + m0 + r;
        if (pp < rhi) {
            int n = n0 + nl;
            outp[(size_t)pp*512 + n] = __float2half(z->sO[r][nl] + g_bias[n]);
        }
    }
}

__device__ void zg_phase(char* SH, int level, int S, int rlo, int rhi, int tid, int cta)
{
    int rows = rhi - rlo, RT = (rows + BM - 1) / BM;
    for (int t5 = cta; t5 < RT*8; t5 += NCTA)
        zg_tile(SH, level, S, rlo, rhi, (t5 >> 3)*BM, (t5 & 7)*BN, tid);
}

/* ------- seq: per-node chain within level (prefetch + warp softmax) ------- */
__device__ void seq_phase(char* SH, int lo, int hi, int S,
                          const float* __restrict__ br, int tid, int cta)
{
    if (cta >= NN) return;
    SeqSh* q = (SeqSh*)SH;
    const int nd = cta;
    const int PM = (MAXS - S + 7) >> 3;
    if (tid == 0) {
        int b0 = g_boff[nd], b1 = g_boff[nd+1];
        int i0 = b0; while (i0 < b1 && g_bucket[i0] < lo) ++i0;
        int i1 = i0; while (i1 < b1 && g_bucket[i1] < hi) ++i1;
        q->i0 = i0; q->i1 = i1;
    }
    __syncthreads();
    const int i0 = q->i0, i1 = q->i1;
    if (i0 >= i1) return;
    int cnt = g_count[nd];
    const int wid = tid >> 5, lid = tid & 31;
    const float brv = br[tid];

    /* load node hist ring into smem once per level */
    #pragma unroll
    for (int r = 0; r < HISTN; ++r)
        q->hist[r][tid] = g_hist[((size_t)nd*HISTN + r)*HH + tid];
    /* prologue: first kq into buffer 0 */
    {
        int s0 = g_bucket[i0];
        const __half* kqp = (s0 < S) ? (g_XF + (size_t)s0*512)
                                     : (g_CH + (size_t)((s0 - S) >> 3)*512);
        q->kq[0][tid] = __half2float(__ldg(kqp + tid));
    }
    __syncthreads();

    for (int i = i0; i < i1; ++i) {
        const int buf   = (i - i0) & 1;
        const int sstep = g_bucket[i];
        /* prefetch next visit's kq into registers (hidden by compute below) */
        float nkq = 0.f;
        const bool hn = (i + 1 < i1);
        if (hn) {
            int s2 = g_bucket[i+1];
            const __half* kqp = (s2 < S) ? (g_XF + (size_t)s2*512)
                                         : (g_CH + (size_t)((s2 - S) >> 3)*512);
            nkq = __half2float(__ldg(kqp + tid));
        }
        const int nv   = (cnt < HISTN) ? cnt : HISTN;
        const int slot = cnt % HISTN;
        const float* kq = q->kq[buf];
        /* logits: warp per slot, 2 passes */
        #pragma unroll
        for (int pass = 0; pass < 2; ++pass) {
            int sl = wid + pass*8;
            if (sl < nv) {
                const float* hp = q->hist[sl];
                float p = 0.f;
                #pragma unroll
                for (int k = 0; k < 8; ++k) { int h = lid + k*32; p += hp[h]*kq[h]; }
                #pragma unroll
                for (int o = 16; o > 0; o >>= 1) p += __shfl_down_sync(0xffffffffu, p, o);
                if (lid == 0) q->logit[sl] = p * 0.0625f;
            }
        }
        __syncthreads();                               /* (1) logits ready */
        /* per-warp redundant softmax + vals (no extra sync) */
        {
            float lg = (lid < nv) ? q->logit[lid] : -1e30f;
            float m = lg;
            #pragma unroll
            for (int o = 16; o > 0; o >>= 1) m = fmaxf(m, __shfl_xor_sync(0xffffffffu, m, o));
            float e = (lid < nv) ? __expf(lg - m) : 0.f;
            float s = e;
            #pragma unroll
            for (int o = 16; o > 0; o >>= 1) s += __shfl_xor_sync(0xffffffffu, s, o);
            float inv = 1.f / s;
            float v = 0.f;
            for (int k = 0; k < nv; ++k) {
                float ak = __shfl_sync(0xffffffffu, e, k) * inv;
                v += ak * q->hist[k][tid];
            }
            q->vals[tid] = v;
        }
        __syncthreads();                               /* (2) vals ready */
        /* ns = vals @ Wr + br : warp w rows 32w..32w+31, lane 8 outputs */
        {
            float a0=0,a1=0,a2=0,a3=0,a4=0,a5=0,a6=0,a7=0;
            const int r0 = wid*32;
            const float4* Wv = (const float4*)g_wr_h;
            #pragma unroll 8
            for (int r = r0; r < r0+32; ++r) {
                float x = q->vals[r];
                float4 w = __ldg(&Wv[(size_t)r*32 + lid]);
                const half2* hp = (const half2*)&w;
                float2 f0 = __half22float2(hp[0]);
                float2 f1 = __half22float2(hp[1]);
                float2 f2 = __half22float2(hp[2]);
                float2 f3 = __half22float2(hp[3]);
                a0 += x*f0.x; a1 += x*f0.y; a2 += x*f1.x; a3 += x*f1.y;
                a4 += x*f2.x; a5 += x*f2.y; a6 += x*f3.x; a7 += x*f3.y;
            }
            float4* sp4 = (float4*)q->spart;
            sp4[(size_t)wid*64 + lid*2 + 0] = make_float4(a0,a1,a2,a3);
            sp4[(size_t)wid*64 + lid*2 + 1] = make_float4(a4,a5,a6,a7);
        }
        /* stage next kq into the other buffer before the partials sync */
        if (hn) q->kq[buf ^ 1][tid] = nkq;
        __syncthreads();                               /* (3) partials + kq staged */
        {
            float r = brv;
            #pragma unroll
            for (int k = 0; k < 8; ++k) r += q->spart[k*HH + tid];
            q->hist[slot][tid] = r;
            if (sstep < PM) g_ns_h[(size_t)sstep*HH + tid] = __float2half(r);
        }
        ++cnt;
        __syncthreads();                               /* (4) hist updated */
    }
    /* spill hist once per level (each thread owns column tid) */
    #pragma unroll
    for (int r = 0; r < HISTN; ++r)
        g_hist[((size_t)nd*HISTN + r)*HH + tid] = q->hist[r][tid];
    if (tid == 0) g_count[nd] = cnt;
}

/* ------------------- mega kernel ------------------------------------------ */
__global__ void __launch_bounds__(TPB2, 4)
k_mega(const float* __restrict__ xa, const int* __restrict__ nbr,
       const float* __restrict__ fm,
       const float* __restrict__ We, const float* __restrict__ be,
       const float* __restrict__ Wq, const float* __restrict__ bq,
       const float* __restrict__ Wk,
       const float* __restrict__ Wr, const float* __restrict__ br,
       const float* __restrict__ Wm, const float* __restrict__ bm,
       const float* __restrict__ Wd, const float* __restrict__ bd,
       const int* __restrict__ nS, float* __restrict__ out)
{
    __shared__ __align__(16) char SH[SHSZ];
    __shared__ unsigned sh_base;
    const int cta = blockIdx.x, tid = threadIdx.x;
    const int S = *nS;
    const int PM = (MAXS - S + 7) >> 3;

    if (tid == 0) sh_base = *(volatile unsigned*)&g_gen;
    __syncthreads();
    unsigned bt = sh_base;

    /* ---- P0: graph (CTA 511) || encode + packs + gemmA (others) ---- */
    if (cta == NCTA-1) {
        graph_phase(SH, nbr, S, tid);
    } else {
        EncSh* es = (EncSh*)SH;
        for (int n = cta; n < NN; n += NCTA-1) {
            if (tid < FF) es->sx[tid] = xa[n*FF + tid];
            __syncthreads();
            float acc = be[tid];
            #pragma unroll 4
            for (int f = 0; f < FF; ++f) acc += es->sx[f] * We[f*HH + tid];
            g_hist[((size_t)n*HISTN + 0)*HH + tid] = acc;
            g_fm_h[(size_t)n*MM + tid] = __float2half(fm[(size_t)n*MM + tid]);
            if (tid == 0) g_count[n] = 1;
            __syncthreads();
        }
        for (int r = cta; r < HH; r += NCTA-1) {
            g_wm1h[(size_t)r*MM + tid] = __float2half(Wm[(size_t)r*MM + tid]);
            float s = Wr[r*HH + tid] + Wr[(HH + r)*HH + tid]
                    + Wr[(2*HH + r)*HH + tid] + Wr[(3*HH + r)*HH + tid];
            g_wr_h[r*HH + tid] = __float2half(s);
        }
        for (int t5 = cta; t5 < 32; t5 += NCTA-1)
            gemmA_tile(SH, t5, Wq, Wk, Wm, bq, bm, tid);
    }
    gbar(cta, ++bt);
    for (int t5 = cta; t5 < 32; t5 += NCTA) gemmD_tile(SH, t5, tid);
    gbar(cta, ++bt);
    zg_phase(SH, -1, S, 0, (S < NN) ? S : NN, tid, cta);
    gbar(cta, ++bt);
    for (int lvl = 0; lvl < NLVL; ++lvl) {
        int lo, hi; level_bounds(S, lvl, &lo, &hi);
        if (lo >= hi) break;
        seq_phase(SH, lo, hi, S, br, tid, cta);
        gbar(cta, ++bt);
        int rhi = (hi < PM) ? hi : PM;
        if (lo < rhi) {                 /* deterministic on all CTAs */
            zg_phase(SH, lvl, S, lo, rhi, tid, cta);
            gbar(cta, ++bt);
        }
    }
    /* ---- out: decoder + log_softmax ---- */
    if (cta < NN) {
        OutSh* o = (OutSh*)SH;
        int cnt  = g_count[cta];
        int slot = (cnt - 1) % HISTN;
        o->fin[tid] = g_hist[((size_t)cta*HISTN + slot)*HH + tid];
        __syncthreads();
        if (tid < PPV*OO) {
            int p = tid >> 6, qo = tid & 63;
            float acc = bd[p*OO + qo];
            #pragma unroll 4
            for (int h = 0; h < HH; ++h) acc += o->fin[h]*Wd[((size_t)p*HH + h)*OO + qo];
            o->lg[tid] = acc;
        }
        __syncthreads();
        if (tid < PPV*OO) {
            int p = tid >> 6, qo = tid & 63;
            float m = -1e30f;
            for (int k = 0; k < OO; ++k) m = fmaxf(m, o->lg[p*OO + k]);
            float sum = 0.f;
            for (int k = 0; k < OO; ++k) sum += expf(o->lg[p*OO + k] - m);
            out[((size_t)p*NN + cta)*OO + qo] = o->lg[tid] - m - logf(sum);
        }
    }
}

/* -------------------------------------------------------------------------- */
extern "C" void kernel_launch(void* const* d_in, const int* in_sizes, int n_in,
                              void* d_out, int out_size)
{
    const float* xa  = (const float*)d_in[0];
    const int*   nbr = (const int*)  d_in[1];
    const float* fm  = (const float*)d_in[2];
    const float* We  = (const float*)d_in[3];
    const float* be  = (const float*)d_in[4];
    const float* Wq  = (const float*)d_in[5];
    const float* bq  = (const float*)d_in[6];
    const float* Wk  = (const float*)d_in[7];
    /* d_in[8] = bk cancels in softmax */
    const float* Wr  = (const float*)d_in[9];
    const float* br  = (const float*)d_in[10];
    const float* Wm  = (const float*)d_in[11];
    const float* bm  = (const float*)d_in[12];
    const float* Wd  = (const float*)d_in[13];
    const float* bd  = (const float*)d_in[14];
    const int*   nS  = (const int*)  d_in[15];

    k_mega<<<NCTA, TPB2>>>(xa, nbr, fm, We, be, Wq, bq, Wk, Wr, br,
                           Wm, bm, Wd, bd, nS, (float*)d_out);
}

// round 16
// speedup vs baseline: 1.5879x; 1.0152x over previous
#include <cuda_runtime.h>
#include <cuda_fp16.h>
#include <mma.h>
#include <math.h>

using namespace nvcuda;

#define NN    512
#define FF    128
#define HH    256
#define MM    256
#define DEGN  8
#define HISTN 10
#define OO    64
#define PPV   2
#define MAXS  (10*NN)     /* 5120 */
#define NLVL  6
#define BM    64
#define BN    64
#define BK    16
#define NCTA  512
#define TPB2  256
#define SHSZ  26688
#define NGRP  16
#define CAPV  160         /* max steps per node per level */

/* -------- persistent scratch (device globals) ----------------------------- */
__device__ float g_hist [NN*HISTN*HH];
__device__ __align__(16) __half g_XF  [NN*512];
__device__ __align__(16) __half g_CH  [((MAXS+7)/8)*512];
__device__ __align__(16) __half g_ns_h[((MAXS+7)/8)*HH];
__device__ __align__(16) __half g_BB  [512*512];   /* rows 0..255 = D, 256..511 = E=[A|Wm2] */
__device__ __align__(16) __half g_wm1h[HH*HH];
__device__ __align__(16) __half g_wr_h[HH*HH];
__device__ __align__(16) __half g_fm_h[NN*MM];
__device__ float g_bias [512];
__device__ int   g_node [MAXS];
__device__ int   g_count[NN];
__device__ __align__(128) unsigned g_grpc[NGRP][32];
__device__ unsigned g_rootc;
__device__ unsigned g_gen;

/* -------- shared overlays -------------------------------------------------- */
struct ZgSh  { __half sA[2][BM][BK]; __half sB[2][BK][BN]; float sO[BM][BN];
               const __half* P1[BM]; const __half* P2[BM]; };
struct SeqSh { float hist[HISTN][HH]; float kq[2][HH]; float vals[HH];
               float spart[8*HH]; float logit[16]; float attn[16];
               int sidx[CAPV]; int scnt; };
struct GaSh  { float sA[16][65]; float sB[16][65]; };
struct EncSh { float sx[FF]; };
struct OutSh { float fin[HH]; float lg[PPV*OO]; };

/* ------------------------- sync helpers ---------------------------------- */
__device__ __forceinline__ unsigned ldg_acq(const unsigned* p) {
    unsigned v;
    asm volatile("ld.acquire.gpu.global.b32 %0, [%1];" : "=r"(v) : "l"(p) : "memory");
    return v;
}
__device__ __forceinline__ void stg_rel(unsigned* p, unsigned v) {
    asm volatile("st.release.gpu.global.b32 [%0], %1;" :: "l"(p), "r"(v) : "memory");
}
__device__ __forceinline__ void gbar(int cta, unsigned target) {
    __syncthreads();
    if (threadIdx.x == 0) {
        __threadfence();
        int grp = cta >> 5;
        if (atomicAdd(&g_grpc[grp][0], 1u) == 31u) {
            *(volatile unsigned*)&g_grpc[grp][0] = 0u;
            __threadfence();
            if (atomicAdd(&g_rootc, 1u) == (unsigned)(NGRP-1)) {
                *(volatile unsigned*)&g_rootc = 0u;
                stg_rel(&g_gen, target);
            }
        }
        while ((int)(ldg_acq(&g_gen) - target) < 0) {}
    }
    __syncthreads();
}

__device__ __forceinline__ void level_bounds(int S, int level, int* plo, int* phi)
{
    int lo = 0, hi = (S < MAXS) ? S : MAXS;
    for (int l = 0; l < level; ++l) {
        lo = hi;
        int h2 = S + 8*hi;
        hi = (h2 > MAXS) ? MAXS : h2;
    }
    *plo = lo; *phi = hi;
}

/* ------------------- gemmA tile: A=Wq@Wk^T / Wm2-pack / bias -------------- */
__device__ void gemmA_tile(char* SH, int t5,
                           const float* __restrict__ Wq, const float* __restrict__ Wk,
                           const float* __restrict__ Wm, const float* __restrict__ bq,
                           const float* __restrict__ bm, int t)
{
    const int bx = t5 >> 2, by = t5 & 3;
    __syncthreads();
    if (bx >= 4) {
        int k0 = (bx-4)*64, j0 = by*64;
        for (int i = t; i < 64*64; i += TPB2) {
            int k = k0 + (i >> 6), j = j0 + (i & 63);
            g_BB[(size_t)(256 + k)*512 + 256 + j] = __float2half(Wm[(size_t)(256 + k)*MM + j]);
        }
        if (bx == 4 && by == 0) {
            int w = t >> 5, l = t & 31;
            for (int r0 = 0; r0 < HH; r0 += 8) {
                int r = r0 + w;
                float p = 0.f;
                #pragma unroll
                for (int k = 0; k < 8; ++k) { int h = l + k*32; p += Wk[(size_t)r*HH + h]*bq[h]; }
                #pragma unroll
                for (int o = 16; o > 0; o >>= 1) p += __shfl_down_sync(0xffffffffu, p, o);
                if (l == 0) g_bias[r] = p;
            }
            g_bias[256 + t] = bm[t];
        }
        return;
    }
    GaSh* ga = (GaSh*)SH;
    const int i0 = bx*64, j0 = by*64;
    const int tx = t & 15, ty = t >> 4;
    float acc[4][4];
    #pragma unroll
    for (int a = 0; a < 4; ++a)
        #pragma unroll
        for (int b = 0; b < 4; ++b) acc[a][b] = 0.f;
    for (int kt = 0; kt < HH; kt += 16) {
        int lr = t >> 2, lh = (t & 3)*4;
        float4 va = *(const float4*)(Wq + (size_t)(i0+lr)*HH + kt + lh);
        ga->sA[lh+0][lr]=va.x; ga->sA[lh+1][lr]=va.y; ga->sA[lh+2][lr]=va.z; ga->sA[lh+3][lr]=va.w;
        float4 vb = *(const float4*)(Wk + (size_t)(j0+lr)*HH + kt + lh);
        ga->sB[lh+0][lr]=vb.x; ga->sB[lh+1][lr]=vb.y; ga->sB[lh+2][lr]=vb.z; ga->sB[lh+3][lr]=vb.w;
        __syncthreads();
        #pragma unroll
        for (int h = 0; h < 16; ++h) {
            float ra[4], rb[4];
            #pragma unroll
            for (int a = 0; a < 4; ++a) ra[a] = ga->sA[h][ty*4 + a];
            #pragma unroll
            for (int b = 0; b < 4; ++b) rb[b] = ga->sB[h][tx*4 + b];
            #pragma unroll
            for (int a = 0; a < 4; ++a)
                #pragma unroll
                for (int b = 0; b < 4; ++b) acc[a][b] += ra[a]*rb[b];
        }
        __syncthreads();
    }
    #pragma unroll
    for (int a = 0; a < 4; ++a)
        #pragma unroll
        for (int b = 0; b < 4; ++b)
            g_BB[(size_t)(256 + i0 + ty*4 + a)*512 + (j0 + tx*4 + b)] = __float2half(acc[a][b]);
}

/* ------------------- gemmD tile: D = Wm1 @ E (2-deep prefetch) ------------ */
__device__ void gemmD_tile(char* SH, int t5, int tid)
{
    ZgSh* z = (ZgSh*)SH;
    const int m0 = (t5 >> 3) * BM, n0 = (t5 & 7) * BN;
    const int wid = tid >> 5, wr = wid & 3, wc = wid >> 2;
    const int ar = tid >> 2, ac = (tid & 3)*4;
    const int brw = tid >> 4, bc = (tid & 15)*4;
    const int KT = HH / BK;
    __syncthreads();
    wmma::fragment<wmma::accumulator,16,16,16,float> acc[2];
    wmma::fill_fragment(acc[0], 0.f);
    wmma::fill_fragment(acc[1], 0.f);
    #define LDA_D(k) (*(const uint2*)(g_wm1h + (size_t)(m0+ar)*HH + (k)*BK + ac))
    #define LDB_D(k) (*(const uint2*)(g_BB + (size_t)(256 + (k)*BK + brw)*512 + n0 + bc))
    uint2 rA[2], rB[2];
    {
        uint2 tA = LDA_D(0), tB = LDB_D(0);
        *(uint2*)&z->sA[0][ar][ac] = tA;
        *(uint2*)&z->sB[0][brw][bc] = tB;
        rA[1] = LDA_D(1); rB[1] = LDB_D(1);
        rA[0] = LDA_D(2); rB[0] = LDB_D(2);
    }
    __syncthreads();
    for (int k = 0; k < KT; ++k) {
        const int p = k & 1, q = p ^ 1;
        if (k + 1 < KT) {
            *(uint2*)&z->sA[q][ar][ac] = rA[q];
            *(uint2*)&z->sB[q][brw][bc] = rB[q];
        }
        if (k + 3 < KT) { rA[q] = LDA_D(k+3); rB[q] = LDB_D(k+3); }
        wmma::fragment<wmma::matrix_a,16,16,16,__half,wmma::row_major> fa;
        wmma::load_matrix_sync(fa, &z->sA[p][wr*16][0], BK);
        #pragma unroll
        for (int j = 0; j < 2; ++j) {
            wmma::fragment<wmma::matrix_b,16,16,16,__half,wmma::row_major> fb;
            wmma::load_matrix_sync(fb, &z->sB[p][0][wc*32 + j*16], BN);
            wmma::mma_sync(acc[j], fa, fb, acc[j]);
        }
        __syncthreads();
    }
    #undef LDA_D
    #undef LDB_D
    wmma::store_matrix_sync(&z->sO[wr*16][wc*32],      acc[0], BN, wmma::mem_row_major);
    wmma::store_matrix_sync(&z->sO[wr*16][wc*32 + 16], acc[1], BN, wmma::mem_row_major);
    __syncthreads();
    for (int idx = tid; idx < BM*BN; idx += TPB2) {
        int r = idx >> 6, nl = idx & 63;
        g_BB[(size_t)(m0 + r)*512 + n0 + nl] = __float2half(z->sO[r][nl]);
    }
}

/* ------------------- zg tile: CH/XF = [NS|W2] @ BB + bias (2-deep) -------- */
__device__ void zg_tile(char* SH, int level, int S, int rlo, int rhi,
                        int m0, int n0, int tid)
{
    ZgSh* z = (ZgSh*)SH;
    __syncthreads();
    if (tid < BM) {
        int p = rlo + m0 + tid;
        if (p < rhi) {
            if (level < 0) {
                z->P1[tid] = 0;
                z->P2[tid] = g_fm_h + (size_t)p*MM;
            } else {
                z->P1[tid] = g_ns_h + (size_t)p*HH;
                z->P2[tid] = (p < S) ? (g_XF + (size_t)p*512 + 256)
                                     : (g_CH + (size_t)((p - S) >> 3)*512 + 256);
            }
        } else { z->P1[tid] = 0; z->P2[tid] = 0; }
    }
    __syncthreads();
    const int wid = tid >> 5, wr = wid & 3, wc = wid >> 2;
    const int ar = tid >> 2, ac = (tid & 3)*4;
    const int brw = tid >> 4, bc = (tid & 15)*4;
    const __half* p1 = z->P1[ar];
    const __half* p2 = z->P2[ar];
    wmma::fragment<wmma::accumulator,16,16,16,float> acc[2];
    wmma::fill_fragment(acc[0], 0.f);
    wmma::fill_fragment(acc[1], 0.f);
    const int KT = 512 / BK;
    #define LDA_Z(k) ({ int kt = (k)*BK; const __half* b_ = (kt < 256) ? p1 : p2; \
                        b_ ? *(const uint2*)(b_ + (kt & 255) + ac) : make_uint2(0u,0u); })
    #define LDB_Z(k) (*(const uint2*)(g_BB + (size_t)((k)*BK + brw)*512 + n0 + bc))
    uint2 rA[2], rB[2];
    {
        uint2 tA = LDA_Z(0), tB = LDB_Z(0);
        *(uint2*)&z->sA[0][ar][ac] = tA;
        *(uint2*)&z->sB[0][brw][bc] = tB;
        rA[1] = LDA_Z(1); rB[1] = LDB_Z(1);
        rA[0] = LDA_Z(2); rB[0] = LDB_Z(2);
    }
    __syncthreads();
    for (int k = 0; k < KT; ++k) {
        const int p = k & 1, q = p ^ 1;
        if (k + 1 < KT) {
            *(uint2*)&z->sA[q][ar][ac] = rA[q];
            *(uint2*)&z->sB[q][brw][bc] = rB[q];
        }
        if (k + 3 < KT) { rA[q] = LDA_Z(k+3); rB[q] = LDB_Z(k+3); }
        wmma::fragment<wmma::matrix_a,16,16,16,__half,wmma::row_major> fa;
        wmma::load_matrix_sync(fa, &z->sA[p][wr*16][0], BK);
        #pragma unroll
        for (int j = 0; j < 2; ++j) {
            wmma::fragment<wmma::matrix_b,16,16,16,__half,wmma::row_major> fb;
            wmma::load_matrix_sync(fb, &z->sB[p][0][wc*32 + j*16], BN);
            wmma::mma_sync(acc[j], fa, fb, acc[j]);
        }
        __syncthreads();
    }
    #undef LDA_Z
    #undef LDB_Z
    wmma::store_matrix_sync(&z->sO[wr*16][wc*32],      acc[0], BN, wmma::mem_row_major);
    wmma::store_matrix_sync(&z->sO[wr*16][wc*32 + 16], acc[1], BN, wmma::mem_row_major);
    __syncthreads();
    __half* outp = (level < 0) ? g_XF : g_CH;
    for (int idx = tid; idx < BM*BN; idx += TPB2) {
        int r = idx >> 6, nl = idx & 63;
        int pp = rlo + m0 + r;
        if (pp < rhi) {
            int n = n0 + nl;
            outp[(size_t)pp*512 + n] = __float2half(z->sO[r][nl] + g_bias[n]);
        }
    }
}

__device__ void zg_phase(char* SH, int level, int S, int rlo, int rhi, int tid, int cta)
{
    int rows = rhi - rlo, RT = (rows + BM - 1) / BM;
    for (int t5 = cta; t5 < RT*8; t5 += NCTA)
        zg_tile(SH, level, S, rlo, rhi, (t5 >> 3)*BM, (t5 & 7)*BN, tid);
}

/* ------- seq: per-node chain within level (direct range scan) ------------- */
__device__ void seq_phase(char* SH, int lo, int hi, int S,
                          const float* __restrict__ br, int tid, int nd)
{
    SeqSh* q = (SeqSh*)SH;
    const int PM = (MAXS - S + 7) >> 3;
    if (tid == 0) q->scnt = 0;
    __syncthreads();
    /* collect this node's steps by scanning the level range */
    for (int j = lo + tid; j < hi; j += TPB2) {
        if (g_node[j] == nd) {
            int pos = atomicAdd(&q->scnt, 1);
            if (pos < CAPV) q->sidx[pos] = j;
        }
    }
    __syncthreads();
    int nsteps = q->scnt; if (nsteps > CAPV) nsteps = CAPV;
    if (nsteps == 0) return;
    if (tid == 0) {                 /* sort ascending = visit order */
        for (int i = 1; i < nsteps; ++i) {
            int v = q->sidx[i], j = i - 1;
            while (j >= 0 && q->sidx[j] > v) { q->sidx[j+1] = q->sidx[j]; --j; }
            q->sidx[j+1] = v;
        }
    }
    /* load hist ring (concurrent with sort; no dependency) */
    #pragma unroll
    for (int r = 0; r < HISTN; ++r)
        q->hist[r][tid] = g_hist[((size_t)nd*HISTN + r)*HH + tid];
    __syncthreads();
    int cnt = g_count[nd];
    const int wid = tid >> 5, lid = tid & 31;
    const float brv = br[tid];
    /* prologue: first kq */
    {
        int s0 = q->sidx[0];
        const __half* kqp = (s0 < S) ? (g_XF + (size_t)s0*512)
                                     : (g_CH + (size_t)((s0 - S) >> 3)*512);
        q->kq[0][tid] = __half2float(__ldg(kqp + tid));
    }
    __syncthreads();

    for (int i = 0; i < nsteps; ++i) {
        const int buf   = i & 1;
        const int sstep = q->sidx[i];
        float nkq = 0.f;
        const bool hn = (i + 1 < nsteps);
        if (hn) {
            int s2 = q->sidx[i+1];
            const __half* kqp = (s2 < S) ? (g_XF + (size_t)s2*512)
                                         : (g_CH + (size_t)((s2 - S) >> 3)*512);
            nkq = __half2float(__ldg(kqp + tid));
        }
        const int nv   = (cnt < HISTN) ? cnt : HISTN;
        const int slot = cnt % HISTN;
        const float* kq = q->kq[buf];
        #pragma unroll
        for (int pass = 0; pass < 2; ++pass) {
            int sl = wid + pass*8;
            if (sl < nv) {
                const float* hp = q->hist[sl];
                float p = 0.f;
                #pragma unroll
                for (int k = 0; k < 8; ++k) { int h = lid + k*32; p += hp[h]*kq[h]; }
                #pragma unroll
                for (int o = 16; o > 0; o >>= 1) p += __shfl_down_sync(0xffffffffu, p, o);
                if (lid == 0) q->logit[sl] = p * 0.0625f;
            }
        }
        __syncthreads();                               /* (1) logits */
        if (tid < 32) {
            float lg = (tid < nv) ? q->logit[tid] : -1e30f;
            float m = lg;
            #pragma unroll
            for (int o = 16; o > 0; o >>= 1) m = fmaxf(m, __shfl_xor_sync(0xffffffffu, m, o));
            float e = (tid < nv) ? __expf(lg - m) : 0.f;
            float s = e;
            #pragma unroll
            for (int o = 16; o > 0; o >>= 1) s += __shfl_xor_sync(0xffffffffu, s, o);
            if (tid < 16) q->attn[tid] = e / s;
        }
        __syncthreads();                               /* (2) attn */
        {
            float v = 0.f;
            #pragma unroll 2
            for (int k = 0; k < nv; ++k) v += q->attn[k]*q->hist[k][tid];
            q->vals[tid] = v;
        }
        __syncthreads();                               /* (3) vals */
        {
            float a0=0,a1=0,a2=0,a3=0,a4=0,a5=0,a6=0,a7=0;
            const int r0 = wid*32;
            const float4* Wv = (const float4*)g_wr_h;
            #pragma unroll 8
            for (int r = r0; r < r0+32; ++r) {
                float x = q->vals[r];
                float4 w = __ldg(&Wv[(size_t)r*32 + lid]);
                const half2* hp = (const half2*)&w;
                float2 f0 = __half22float2(hp[0]);
                float2 f1 = __half22float2(hp[1]);
                float2 f2 = __half22float2(hp[2]);
                float2 f3 = __half22float2(hp[3]);
                a0 += x*f0.x; a1 += x*f0.y; a2 += x*f1.x; a3 += x*f1.y;
                a4 += x*f2.x; a5 += x*f2.y; a6 += x*f3.x; a7 += x*f3.y;
            }
            float4* sp4 = (float4*)q->spart;
            sp4[(size_t)wid*64 + lid*2 + 0] = make_float4(a0,a1,a2,a3);
            sp4[(size_t)wid*64 + lid*2 + 1] = make_float4(a4,a5,a6,a7);
        }
        if (hn) q->kq[buf ^ 1][tid] = nkq;
        __syncthreads();                               /* (4) partials + next kq */
        {
            float r = brv;
            #pragma unroll
            for (int k = 0; k < 8; ++k) r += q->spart[k*HH + tid];
            q->hist[slot][tid] = r;
            if (sstep < PM) g_ns_h[(size_t)sstep*HH + tid] = __float2half(r);
        }
        ++cnt;
        __syncthreads();                               /* (5) hist updated */
    }
    #pragma unroll
    for (int r = 0; r < HISTN; ++r)
        g_hist[((size_t)nd*HISTN + r)*HH + tid] = q->hist[r][tid];
    if (tid == 0) g_count[nd] = cnt;
}

/* ------------------- mega kernel ------------------------------------------ */
__global__ void __launch_bounds__(TPB2, 4)
k_mega(const float* __restrict__ xa, const int* __restrict__ nbr,
       const float* __restrict__ fm,
       const float* __restrict__ We, const float* __restrict__ be,
       const float* __restrict__ Wq, const float* __restrict__ bq,
       const float* __restrict__ Wk,
       const float* __restrict__ Wr, const float* __restrict__ br,
       const float* __restrict__ Wm, const float* __restrict__ bm,
       const float* __restrict__ Wd, const float* __restrict__ bd,
       const int* __restrict__ nS, float* __restrict__ out)
{
    __shared__ __align__(16) char SH[SHSZ];
    __shared__ unsigned sh_base;
    const int cta = blockIdx.x, tid = threadIdx.x;
    const int S = *nS;
    const int PM = (MAXS - S + 7) >> 3;

    if (tid == 0) sh_base = *(volatile unsigned*)&g_gen;
    __syncthreads();
    unsigned bt = sh_base;

    /* ---- B0: node init [0,S), encode (1 node/CTA), packs, gemmA ---------- */
    for (int e = cta*TPB2 + tid; e < S && e < MAXS; e += NCTA*TPB2) g_node[e] = e;
    {
        EncSh* es = (EncSh*)SH;
        const int n = cta;
        if (tid < FF) es->sx[tid] = xa[n*FF + tid];
        __syncthreads();
        float acc = be[tid];
        #pragma unroll 4
        for (int f = 0; f < FF; ++f) acc += es->sx[f] * We[f*HH + tid];
        g_hist[((size_t)n*HISTN + 0)*HH + tid] = acc;
        g_fm_h[(size_t)n*MM + tid] = __float2half(fm[(size_t)n*MM + tid]);
        if (tid == 0) g_count[n] = 1;
        __syncthreads();
    }
    if (cta < HH) {
        const int r = cta;
        g_wm1h[(size_t)r*MM + tid] = __float2half(Wm[(size_t)r*MM + tid]);
        float s = Wr[r*HH + tid] + Wr[(HH + r)*HH + tid]
                + Wr[(2*HH + r)*HH + tid] + Wr[(3*HH + r)*HH + tid];
        g_wr_h[r*HH + tid] = __float2half(s);
    }
    if (cta >= NCTA-32) gemmA_tile(SH, cta - (NCTA-32), Wq, Wk, Wm, bq, bm, tid);
    gbar(cta, ++bt);

    /* ---- expansion phases (fused: lvl1 += gemmD, lvl2 += XF seed) --------- */
    for (int lvl = 1; lvl < NLVL; ++lvl) {
        int lo, hi; level_bounds(S, lvl, &lo, &hi);
        if (lo >= hi) break;
        for (int e = lo + cta*TPB2 + tid; e < hi; e += NCTA*TPB2) {
            int src = (e - S) >> 3;
            g_node[e] = nbr[g_node[src]*DEGN + ((e - S) & 7)];
        }
        if (lvl == 1 && cta < 32) gemmD_tile(SH, cta, tid);
        if (lvl == 2) zg_phase(SH, -1, S, 0, (S < NN) ? S : NN, tid, cta);
        gbar(cta, ++bt);
    }

    /* ---- levels: seq -> zg ----------------------------------------------- */
    for (int lvl = 0; lvl < NLVL; ++lvl) {
        int lo, hi; level_bounds(S, lvl, &lo, &hi);
        if (lo >= hi) break;
        seq_phase(SH, lo, hi, S, br, tid, cta);
        gbar(cta, ++bt);
        int rhi = (hi < PM) ? hi : PM;
        if (lo < rhi) {
            zg_phase(SH, lvl, S, lo, rhi, tid, cta);
            gbar(cta, ++bt);
        }
    }

    /* ---- out: decoder + log_softmax -------------------------------------- */
    {
        OutSh* o = (OutSh*)SH;
        int cnt  = g_count[cta];
        int slot = (cnt - 1) % HISTN;
        o->fin[tid] = g_hist[((size_t)cta*HISTN + slot)*HH + tid];
        __syncthreads();
        if (tid < PPV*OO) {
            int p = tid >> 6, qo = tid & 63;
            float acc = bd[p*OO + qo];
            #pragma unroll 4
            for (int h = 0; h < HH; ++h) acc += o->fin[h]*Wd[((size_t)p*HH + h)*OO + qo];
            o->lg[tid] = acc;
        }
        __syncthreads();
        if (tid < PPV*OO) {
            int p = tid >> 6, qo = tid & 63;
            float m = -1e30f;
            for (int k = 0; k < OO; ++k) m = fmaxf(m, o->lg[p*OO + k]);
            float sum = 0.f;
            for (int k = 0; k < OO; ++k) sum += expf(o->lg[p*OO + k] - m);
            out[((size_t)p*NN + cta)*OO + qo] = o->lg[tid] - m - logf(sum);
        }
    }
}

/* -------------------------------------------------------------------------- */
extern "C" void kernel_launch(void* const* d_in, const int* in_sizes, int n_in,
                              void* d_out, int out_size)
{
    const float* xa  = (const float*)d_in[0];
    const int*   nbr = (const int*)  d_in[1];
    const float* fm  = (const float*)d_in[2];
    const float* We  = (const float*)d_in[3];
    const float* be  = (const float*)d_in[4];
    const float* Wq  = (const float*)d_in[5];
    const float* bq  = (const float*)d_in[6];
    const float* Wk  = (const float*)d_in[7];
    /* d_in[8] = bk cancels in softmax */
    const float* Wr  = (const float*)d_in[9];
    const float* br  = (const float*)d_in[10];
    const float* Wm  = (const float*)d_in[11];
    const float* bm  = (const float*)d_in[12];
    const float* Wd  = (const float*)d_in[13];
    const float* bd  = (const float*)d_in[14];
    const int*   nS  = (const int*)  d_in[15];

    k_mega<<<NCTA, TPB2>>>(xa, nbr, fm, We, be, Wq, bq, Wk, Wr, br,
                           Wm, bm, Wd, bd, nS, (float*)d_out);
}